// round 6
// baseline (speedup 1.0000x reference)
#include <cuda_runtime.h>
#include <math.h>

#define L 64
static const int NMAX = 100352;
static const int EMAX = 1605632;

__device__ __align__(16) float g_deg[NMAX];
__device__ __align__(16) float g_dinv[NMAX];
__device__ __align__(16) float g_rcp[NMAX];
__device__ int   g_cnti[NMAX];
__device__ int   g_offs[NMAX];
__device__ int   g_cursor[NMAX];
__device__ int   g_bsums[1024];
__device__ __align__(16) uint2 g_csr[EMAX];   // .x = row idx, .y = norm bits
__device__ __align__(16) float g_h [(size_t)NMAX * L];
__device__ __align__(16) float g_t0[(size_t)NMAX * L];
__device__ __align__(16) float g_t1[(size_t)NMAX * L];
__device__ int   g_is64;

// ---- packed f32x2 helpers (sm_100+) ----------------------------------------
__device__ __forceinline__ unsigned long long dup2(float x) {
    unsigned long long d;
    asm("mov.b64 %0, {%1, %1};" : "=l"(d) : "f"(x));
    return d;
}
__device__ __forceinline__ void ffma2(unsigned long long& d,
                                      unsigned long long a, unsigned long long b) {
    asm("fma.rn.f32x2 %0, %1, %2, %0;" : "+l"(d) : "l"(a), "l"(b));
}
__device__ __forceinline__ float2 unpack2(unsigned long long d) {
    float2 f;
    asm("mov.b64 {%0, %1}, %2;" : "=f"(f.x), "=f"(f.y) : "l"(d));
    return f;
}

__global__ void k_detect(const unsigned int* er) {
    if (blockIdx.x == 0 && threadIdx.x == 0) {
        int ok = 1;
        #pragma unroll
        for (int i = 0; i < 64; i++)
            if (er[2 * i + 1] != 0u) ok = 0;
        g_is64 = ok;
    }
}

__device__ __forceinline__ int ld_idx(const void* p, int e, int is64) {
    if (is64) return (int)((const long long*)p)[e];
    return ((const int*)p)[e];
}

__global__ void k_zero2(float* pf, int* pi, int n) {
    int i = blockIdx.x * blockDim.x + threadIdx.x;
    if (i < n) { pf[i] = 0.0f; pi[i] = 0; }
}

__global__ void k_deg_cnt(const float* __restrict__ attr, const void* colp, int E) {
    int is64 = g_is64;
    int e = blockIdx.x * blockDim.x + threadIdx.x;
    if (e < E) {
        int c = ld_idx(colp, e, is64);
        atomicAdd(&g_deg[c], attr[e]);
        atomicAdd(&g_cnti[c], 1);
    }
}

__global__ void k_dinv(int N) {
    int n = blockIdx.x * blockDim.x + threadIdx.x;
    if (n < N) {
        float d = g_deg[n];
        g_dinv[n] = (d > 0.0f) ? rsqrtf(fmaxf(d, 1e-30f)) : 0.0f;
        g_rcp[n] = 1.0f / fmaxf((float)g_cnti[n], 1.0f);
    }
}

// ---------------- prefix scan over counts -----------------------------------
__global__ void k_scan1(int N) {
    __shared__ int wsum[8];
    int t = threadIdx.x;
    int base = blockIdx.x * 1024 + t * 4;
    int v0 = 0, v1 = 0, v2 = 0, v3 = 0;
    if (base + 0 < N) v0 = g_cnti[base + 0];
    if (base + 1 < N) v1 = g_cnti[base + 1];
    if (base + 2 < N) v2 = g_cnti[base + 2];
    if (base + 3 < N) v3 = g_cnti[base + 3];
    int s = v0 + v1 + v2 + v3;
    int lane = t & 31, warp = t >> 5;
    int x = s;
    #pragma unroll
    for (int o = 1; o < 32; o <<= 1) {
        int y = __shfl_up_sync(0xffffffffu, x, o);
        if (lane >= o) x += y;
    }
    if (lane == 31) wsum[warp] = x;
    __syncthreads();
    if (warp == 0 && lane < 8) {
        int w = wsum[lane];
        #pragma unroll
        for (int o = 1; o < 8; o <<= 1) {
            int y = __shfl_up_sync(0x000000ffu, w, o);
            if (lane >= o) w += y;
        }
        wsum[lane] = w;
    }
    __syncthreads();
    int excl = x - s + (warp > 0 ? wsum[warp - 1] : 0);
    int r = excl;
    r += v0; if (base + 0 < N) g_offs[base + 0] = r;
    r += v1; if (base + 1 < N) g_offs[base + 1] = r;
    r += v2; if (base + 2 < N) g_offs[base + 2] = r;
    r += v3; if (base + 3 < N) g_offs[base + 3] = r;
    if (t == 255) g_bsums[blockIdx.x] = excl + s;
}

__global__ void k_scan2(int nb) {
    if (threadIdx.x == 0 && blockIdx.x == 0) {
        int run = 0;
        for (int i = 0; i < nb; i++) { int t = g_bsums[i]; g_bsums[i] = run; run += t; }
    }
}

__global__ void k_scan3(int N) {
    int i = blockIdx.x * blockDim.x + threadIdx.x;
    if (i < N) {
        int excl = g_offs[i] + g_bsums[i >> 10] - g_cnti[i];
        g_offs[i] = excl;
        g_cursor[i] = excl;
    }
}

// CSR fill with inline GCN norm: rec.y = dinv[r]*attr*dinv[c]
__global__ void k_csr_fill(const float* __restrict__ attr, const void* rowp,
                           const void* colp, int E) {
    int is64 = g_is64;
    int e = blockIdx.x * blockDim.x + threadIdx.x;
    if (e < E) {
        int r = ld_idx(rowp, e, is64);
        int c = ld_idx(colp, e, is64);
        int p = atomicAdd(&g_cursor[c], 1);
        uint2 rec;
        rec.x = (unsigned int)r;
        rec.y = __float_as_uint(g_dinv[r] * attr[e] * g_dinv[c]);
        g_csr[p] = rec;
    }
}

__global__ void k_enc(const float* __restrict__ x, const float* __restrict__ w,
                      const float* __restrict__ b, int N) {
    int i = blockIdx.x * blockDim.x + threadIdx.x;
    if (i < N * L) {
        int n = i >> 6, f = i & 63;
        g_h[i] = x[n] * w[f] + b[f];
    }
}

// ---- aggregation: agg[n] = rcp[n] * sum_e norm_e * hin[row_e]  (warp/node) --
__global__ void __launch_bounds__(256)
k_agg(const float* __restrict__ hin, float* __restrict__ aggo, int N) {
    int warp = threadIdx.x >> 5, lane = threadIdx.x & 31;
    int n = blockIdx.x * 8 + warp;
    if (n >= N) return;
    int lane2 = lane * 2;
    int st = g_offs[n];
    int en = st + g_cnti[n];
    float ax0 = 0.f, ay0 = 0.f, ax1 = 0.f, ay1 = 0.f;
    int k = st;
    #pragma unroll 1
    for (; k + 4 <= en; k += 4) {
        uint2 e0 = g_csr[k + 0];
        uint2 e1 = g_csr[k + 1];
        uint2 e2 = g_csr[k + 2];
        uint2 e3 = g_csr[k + 3];
        float2 v0 = *(const float2*)(hin + ((size_t)e0.x << 6) + lane2);
        float2 v1 = *(const float2*)(hin + ((size_t)e1.x << 6) + lane2);
        float2 v2 = *(const float2*)(hin + ((size_t)e2.x << 6) + lane2);
        float2 v3 = *(const float2*)(hin + ((size_t)e3.x << 6) + lane2);
        float f0 = __uint_as_float(e0.y), f1 = __uint_as_float(e1.y);
        float f2 = __uint_as_float(e2.y), f3 = __uint_as_float(e3.y);
        ax0 += v0.x * f0; ay0 += v0.y * f0;
        ax1 += v1.x * f1; ay1 += v1.y * f1;
        ax0 += v2.x * f2; ay0 += v2.y * f2;
        ax1 += v3.x * f3; ay1 += v3.y * f3;
    }
    #pragma unroll 1
    for (; k < en; k++) {
        uint2 rec = g_csr[k];
        float nm = __uint_as_float(rec.y);
        float2 v = *(const float2*)(hin + ((size_t)rec.x << 6) + lane2);
        ax0 += v.x * nm; ay0 += v.y * nm;
    }
    float rcp = g_rcp[n];
    float2 o;
    o.x = (ax0 + ax1) * rcp;
    o.y = (ay0 + ay1) * rcp;
    *(float2*)(aggo + ((size_t)n << 6) + lane2) = o;
}

// ---- GEMM: 64 rows/block, 256 threads, 2x8 tile/thread, f32x2 FMA ----------
// Stores/loads unconditionally: grid*64 <= NMAX, buffers are NMAX rows.
template<bool RELU>
__global__ void __launch_bounds__(256)
k_gemm(const float* __restrict__ X, const float* __restrict__ W,
       const float* __restrict__ bias, float* __restrict__ Y) {
    __shared__ float Ws[64][64];
    __shared__ float Xs[64][68];
    int tid = threadIdx.x;
    const float4* W4 = (const float4*)W;
    #pragma unroll
    for (int i = 0; i < 4; i++) {
        int idx = tid + i * 256;
        *(float4*)&Ws[idx >> 4][(idx & 15) * 4] = W4[idx];
    }
    size_t base = (size_t)blockIdx.x * (64 * 64);
    const float4* X4 = (const float4*)(X + base);
    #pragma unroll
    for (int i = 0; i < 4; i++) {
        int idx = tid + i * 256;
        *(float4*)&Xs[idx >> 4][(idx & 15) * 4] = X4[idx];
    }
    __syncthreads();
    int tr = (tid >> 3) * 2;   // 32 groups of 2 rows
    int tc = (tid & 7) * 8;    // 8 groups of 8 cols
    unsigned long long a0[4], a1[4];
    #pragma unroll
    for (int p = 0; p < 4; p++) { a0[p] = 0ull; a1[p] = 0ull; }
    #pragma unroll 4
    for (int k = 0; k < 64; k++) {
        ulonglong2 wA = *(const ulonglong2*)&Ws[k][tc];      // cols tc..tc+3
        ulonglong2 wB = *(const ulonglong2*)&Ws[k][tc + 4];  // cols tc+4..tc+7
        unsigned long long x0 = dup2(Xs[tr + 0][k]);
        unsigned long long x1 = dup2(Xs[tr + 1][k]);
        ffma2(a0[0], x0, wA.x); ffma2(a0[1], x0, wA.y);
        ffma2(a0[2], x0, wB.x); ffma2(a0[3], x0, wB.y);
        ffma2(a1[0], x1, wA.x); ffma2(a1[1], x1, wA.y);
        ffma2(a1[2], x1, wB.x); ffma2(a1[3], x1, wB.y);
    }
    float bb[8];
    #pragma unroll
    for (int j = 0; j < 8; j++) bb[j] = 0.0f;
    if (bias) {
        float4 bA = *(const float4*)(bias + tc);
        float4 bB = *(const float4*)(bias + tc + 4);
        bb[0] = bA.x; bb[1] = bA.y; bb[2] = bA.z; bb[3] = bA.w;
        bb[4] = bB.x; bb[5] = bB.y; bb[6] = bB.z; bb[7] = bB.w;
    }
    #pragma unroll
    for (int r = 0; r < 2; r++) {
        unsigned long long* ar = r ? a1 : a0;
        float4 oA, oB;
        float2 c0 = unpack2(ar[0]);
        float2 c1 = unpack2(ar[1]);
        float2 c2 = unpack2(ar[2]);
        float2 c3 = unpack2(ar[3]);
        oA.x = c0.x + bb[0]; oA.y = c0.y + bb[1];
        oA.z = c1.x + bb[2]; oA.w = c1.y + bb[3];
        oB.x = c2.x + bb[4]; oB.y = c2.y + bb[5];
        oB.z = c3.x + bb[6]; oB.w = c3.y + bb[7];
        if (RELU) {
            oA.x = fmaxf(oA.x, 0.f); oA.y = fmaxf(oA.y, 0.f);
            oA.z = fmaxf(oA.z, 0.f); oA.w = fmaxf(oA.w, 0.f);
            oB.x = fmaxf(oB.x, 0.f); oB.y = fmaxf(oB.y, 0.f);
            oB.z = fmaxf(oB.z, 0.f); oB.w = fmaxf(oB.w, 0.f);
        }
        float* y = Y + base + (size_t)(tr + r) * 64 + tc;
        *(float4*)(y + 0) = oA;
        *(float4*)(y + 4) = oB;
    }
}

// ---- decoder: out[e] = relu(A[r]+B[c]+b1).w2 + b2 ; softplus on diag -------
#define DEC_EPW 8
__global__ void __launch_bounds__(256)
k_dec(const void* rowp, const void* colp,
      const float* __restrict__ b1, const float* __restrict__ w2,
      const float* __restrict__ b2, float* __restrict__ out, int E) {
    int is64 = g_is64;
    int gw   = (blockIdx.x * blockDim.x + threadIdx.x) >> 5;
    int lane = threadIdx.x & 31;
    int lane2 = lane * 2;
    float2 bias = *(const float2*)(b1 + lane2);
    float2 w    = *(const float2*)(w2 + lane2);
    float  bout = b2[0];
    int e0 = gw * DEC_EPW;
    if (e0 >= E) return;
    int m = E - e0; if (m > DEC_EPW) m = DEC_EPW;

    int   rr[DEC_EPW], cc[DEC_EPW];
    float s[DEC_EPW];
    #pragma unroll
    for (int j = 0; j < DEC_EPW; j++) {
        if (j < m) {
            int r = ld_idx(rowp, e0 + j, is64);
            int c = ld_idx(colp, e0 + j, is64);
            rr[j] = r; cc[j] = c;
            float2 a  = *(const float2*)(g_t0 + ((size_t)r << 6) + lane2);
            float2 bb = *(const float2*)(g_t1 + ((size_t)c << 6) + lane2);
            s[j] = fmaxf(a.x + bb.x + bias.x, 0.f) * w.x
                 + fmaxf(a.y + bb.y + bias.y, 0.f) * w.y;
        }
    }
    #pragma unroll
    for (int j = 0; j < DEC_EPW; j++) {
        if (j < m) {
            float v = s[j];
            #pragma unroll
            for (int off = 16; off; off >>= 1)
                v += __shfl_down_sync(0xffffffffu, v, off);
            if (lane == 0) {
                float val = v + bout;
                if (rr[j] == cc[j])
                    val = fmaxf(val, 0.f) + log1pf(expf(-fabsf(val)));
                out[e0 + j] = val;
            }
        }
    }
}

extern "C" void kernel_launch(void* const* d_in, const int* in_sizes, int n_in,
                              void* d_out, int out_size) {
    const float* x        = (const float*)d_in[0];
    const float* eattr    = (const float*)d_in[1];
    const float* w_enc    = (const float*)d_in[2];
    const float* b_enc    = (const float*)d_in[3];
    const float* conv1_w  = (const float*)d_in[4];
    const float* conv1_b  = (const float*)d_in[5];
    const float* conv2_w  = (const float*)d_in[6];
    const float* conv2_b  = (const float*)d_in[7];
    const float* dec_w1   = (const float*)d_in[8];
    const float* dec_b1   = (const float*)d_in[9];
    const float* dec_w2   = (const float*)d_in[10];
    const float* dec_b2   = (const float*)d_in[11];
    const void*  rowp     = d_in[12];
    const void*  colp     = d_in[13];
    float* out = (float*)d_out;

    const int N = in_sizes[0];
    const int E = in_sizes[1];

    float *p_deg, *p_h, *p_t0, *p_t1;
    int *p_cnti;
    cudaGetSymbolAddress((void**)&p_deg, g_deg);
    cudaGetSymbolAddress((void**)&p_h,   g_h);
    cudaGetSymbolAddress((void**)&p_t0,  g_t0);
    cudaGetSymbolAddress((void**)&p_t1,  g_t1);
    cudaGetSymbolAddress((void**)&p_cnti, g_cnti);

    const int TB = 256;
    int eb  = (E + TB - 1) / TB;
    int nb  = (N + TB - 1) / TB;
    int nfb = (N * L + TB - 1) / TB;
    int gb  = (N + 63) / 64;
    int ab  = (N + 7) / 8;
    int nsb = (N + 1023) / 1024;
    int db  = (int)(((long long)E + DEC_EPW * 8 - 1) / (DEC_EPW * 8));

    k_detect<<<1, 64>>>((const unsigned int*)rowp);

    k_zero2<<<nb, TB>>>(p_deg, p_cnti, N);
    k_deg_cnt<<<eb, TB>>>(eattr, colp, E);
    k_dinv<<<nb, TB>>>(N);

    k_scan1<<<nsb, 256>>>(N);
    k_scan2<<<1, 32>>>(nsb);
    k_scan3<<<nb, TB>>>(N);
    k_csr_fill<<<eb, TB>>>(eattr, rowp, colp, E);

    k_enc<<<nfb, TB>>>(x, w_enc, b_enc, N);

    // 6 GCN layers: agg (cur -> t1), gemm+bias+relu (t1 -> nxt)
    float* cur = p_h;
    float* nxt = p_t0;
    for (int i = 0; i < 3; i++) {
        k_agg<<<ab, TB>>>(cur, p_t1, N);
        k_gemm<true><<<gb, TB>>>(p_t1, conv1_w + (size_t)i * 4096,
                                 conv1_b + (size_t)i * 64, nxt);
        { float* t = cur; cur = nxt; nxt = t; }
        k_agg<<<ab, TB>>>(cur, p_t1, N);
        k_gemm<true><<<gb, TB>>>(p_t1, conv2_w + (size_t)i * 4096,
                                 conv2_b + (size_t)i * 64, nxt);
        { float* t = cur; cur = nxt; nxt = t; }
    }
    // cur == p_h after 6 layers

    k_gemm<false><<<gb, TB>>>(cur, dec_w1,        (const float*)0, p_t0);
    k_gemm<false><<<gb, TB>>>(cur, dec_w1 + 4096, (const float*)0, p_t1);
    k_dec<<<db, TB>>>(rowp, colp, dec_b1, dec_w2, dec_b2, out, E);
}

// round 7
// speedup vs baseline: 1.4447x; 1.4447x over previous
#include <cuda_runtime.h>
#include <math.h>

#define L 64
static const int NMAX = 100352;
static const int EMAX = 1605632;

__device__ __align__(16) float g_deg[NMAX];
__device__ __align__(16) float g_dinv[NMAX];
__device__ __align__(16) float g_rcp[NMAX];
__device__ int   g_cnti[NMAX];
__device__ int   g_offs[NMAX];
__device__ int   g_cursor[NMAX];
__device__ int   g_bsums[1024];
__device__ __align__(16) uint2 g_csr[EMAX];   // .x = row idx, .y = norm bits
__device__ __align__(16) float g_h [(size_t)NMAX * L];
__device__ __align__(16) float g_t0[(size_t)NMAX * L];
__device__ __align__(16) float g_t1[(size_t)NMAX * L];
__device__ int   g_is64;

__global__ void k_detect(const unsigned int* er) {
    if (blockIdx.x == 0 && threadIdx.x == 0) {
        int ok = 1;
        #pragma unroll
        for (int i = 0; i < 64; i++)
            if (er[2 * i + 1] != 0u) ok = 0;
        g_is64 = ok;
    }
}

__device__ __forceinline__ int ld_idx(const void* p, int e, int is64) {
    if (is64) return (int)((const long long*)p)[e];
    return ((const int*)p)[e];
}

__global__ void k_zero2(float* pf, int* pi, int n) {
    int i = blockIdx.x * blockDim.x + threadIdx.x;
    if (i < n) { pf[i] = 0.0f; pi[i] = 0; }
}

__global__ void k_deg_cnt(const float* __restrict__ attr, const void* colp, int E) {
    int is64 = g_is64;
    int e = blockIdx.x * blockDim.x + threadIdx.x;
    if (e < E) {
        int c = ld_idx(colp, e, is64);
        atomicAdd(&g_deg[c], attr[e]);
        atomicAdd(&g_cnti[c], 1);
    }
}

__global__ void k_dinv(int N) {
    int n = blockIdx.x * blockDim.x + threadIdx.x;
    if (n < N) {
        float d = g_deg[n];
        g_dinv[n] = (d > 0.0f) ? rsqrtf(fmaxf(d, 1e-30f)) : 0.0f;
        g_rcp[n] = 1.0f / fmaxf((float)g_cnti[n], 1.0f);
    }
}

// ---------------- prefix scan over counts -----------------------------------
__global__ void k_scan1(int N) {
    __shared__ int wsum[8];
    int t = threadIdx.x;
    int base = blockIdx.x * 1024 + t * 4;
    int v0 = 0, v1 = 0, v2 = 0, v3 = 0;
    if (base + 0 < N) v0 = g_cnti[base + 0];
    if (base + 1 < N) v1 = g_cnti[base + 1];
    if (base + 2 < N) v2 = g_cnti[base + 2];
    if (base + 3 < N) v3 = g_cnti[base + 3];
    int s = v0 + v1 + v2 + v3;
    int lane = t & 31, warp = t >> 5;
    int x = s;
    #pragma unroll
    for (int o = 1; o < 32; o <<= 1) {
        int y = __shfl_up_sync(0xffffffffu, x, o);
        if (lane >= o) x += y;
    }
    if (lane == 31) wsum[warp] = x;
    __syncthreads();
    if (warp == 0 && lane < 8) {
        int w = wsum[lane];
        #pragma unroll
        for (int o = 1; o < 8; o <<= 1) {
            int y = __shfl_up_sync(0x000000ffu, w, o);
            if (lane >= o) w += y;
        }
        wsum[lane] = w;
    }
    __syncthreads();
    int excl = x - s + (warp > 0 ? wsum[warp - 1] : 0);
    int r = excl;
    r += v0; if (base + 0 < N) g_offs[base + 0] = r;
    r += v1; if (base + 1 < N) g_offs[base + 1] = r;
    r += v2; if (base + 2 < N) g_offs[base + 2] = r;
    r += v3; if (base + 3 < N) g_offs[base + 3] = r;
    if (t == 255) g_bsums[blockIdx.x] = excl + s;
}

__global__ void k_scan2(int nb) {
    if (threadIdx.x == 0 && blockIdx.x == 0) {
        int run = 0;
        for (int i = 0; i < nb; i++) { int t = g_bsums[i]; g_bsums[i] = run; run += t; }
    }
}

__global__ void k_scan3(int N) {
    int i = blockIdx.x * blockDim.x + threadIdx.x;
    if (i < N) {
        int excl = g_offs[i] + g_bsums[i >> 10] - g_cnti[i];
        g_offs[i] = excl;
        g_cursor[i] = excl;
    }
}

// CSR fill with inline GCN norm: rec.y = dinv[r]*attr*dinv[c]
__global__ void k_csr_fill(const float* __restrict__ attr, const void* rowp,
                           const void* colp, int E) {
    int is64 = g_is64;
    int e = blockIdx.x * blockDim.x + threadIdx.x;
    if (e < E) {
        int r = ld_idx(rowp, e, is64);
        int c = ld_idx(colp, e, is64);
        int p = atomicAdd(&g_cursor[c], 1);
        uint2 rec;
        rec.x = (unsigned int)r;
        rec.y = __float_as_uint(g_dinv[r] * attr[e] * g_dinv[c]);
        g_csr[p] = rec;
    }
}

__global__ void k_enc(const float* __restrict__ x, const float* __restrict__ w,
                      const float* __restrict__ b, int N) {
    int i = blockIdx.x * blockDim.x + threadIdx.x;
    if (i < N * L) {
        int n = i >> 6, f = i & 63;
        g_h[i] = x[n] * w[f] + b[f];
    }
}

// ---- aggregation: agg[n] = rcp[n] * sum_e norm_e * hin[row_e]  (warp/node) --
__global__ void __launch_bounds__(256)
k_agg(const float* __restrict__ hin, float* __restrict__ aggo, int N) {
    int warp = threadIdx.x >> 5, lane = threadIdx.x & 31;
    int n = blockIdx.x * 8 + warp;
    if (n >= N) return;
    int lane2 = lane * 2;
    int st = g_offs[n];
    int en = st + g_cnti[n];
    float ax0 = 0.f, ay0 = 0.f, ax1 = 0.f, ay1 = 0.f;
    int k = st;
    #pragma unroll 1
    for (; k + 4 <= en; k += 4) {
        uint2 e0 = g_csr[k + 0];
        uint2 e1 = g_csr[k + 1];
        uint2 e2 = g_csr[k + 2];
        uint2 e3 = g_csr[k + 3];
        float2 v0 = *(const float2*)(hin + ((size_t)e0.x << 6) + lane2);
        float2 v1 = *(const float2*)(hin + ((size_t)e1.x << 6) + lane2);
        float2 v2 = *(const float2*)(hin + ((size_t)e2.x << 6) + lane2);
        float2 v3 = *(const float2*)(hin + ((size_t)e3.x << 6) + lane2);
        float f0 = __uint_as_float(e0.y), f1 = __uint_as_float(e1.y);
        float f2 = __uint_as_float(e2.y), f3 = __uint_as_float(e3.y);
        ax0 += v0.x * f0; ay0 += v0.y * f0;
        ax1 += v1.x * f1; ay1 += v1.y * f1;
        ax0 += v2.x * f2; ay0 += v2.y * f2;
        ax1 += v3.x * f3; ay1 += v3.y * f3;
    }
    #pragma unroll 1
    for (; k < en; k++) {
        uint2 rec = g_csr[k];
        float nm = __uint_as_float(rec.y);
        float2 v = *(const float2*)(hin + ((size_t)rec.x << 6) + lane2);
        ax0 += v.x * nm; ay0 += v.y * nm;
    }
    float rcp = g_rcp[n];
    float2 o;
    o.x = (ax0 + ax1) * rcp;
    o.y = (ay0 + ay1) * rcp;
    *(float2*)(aggo + ((size_t)n << 6) + lane2) = o;
}

// ---- GEMM: Y[64 rows] = X @ W (+bias, relu). Register-blocked 4x4 (R4). ----
// Stores unconditionally: buffers are NMAX=100352 rows, grid*64 <= NMAX.
template<bool RELU>
__global__ void __launch_bounds__(256)
k_gemm(const float* __restrict__ X, const float* __restrict__ W,
       const float* __restrict__ bias, float* __restrict__ Y) {
    __shared__ float Ws[64][64];
    __shared__ float Xs[64][68];
    int tid = threadIdx.x;
    const float4* W4 = (const float4*)W;
    #pragma unroll
    for (int i = 0; i < 4; i++) {
        int idx = tid + i * 256;
        float4 v = W4[idx];
        *(float4*)&Ws[idx >> 4][(idx & 15) * 4] = v;
    }
    size_t base = (size_t)blockIdx.x * (64 * 64);
    const float4* X4 = (const float4*)(X + base);
    #pragma unroll
    for (int i = 0; i < 4; i++) {
        int idx = tid + i * 256;
        float4 v = X4[idx];
        *(float4*)&Xs[idx >> 4][(idx & 15) * 4] = v;
    }
    __syncthreads();
    int tr = (tid >> 4) * 4;
    int tc = (tid & 15) * 4;
    float a00=0,a01=0,a02=0,a03=0, a10=0,a11=0,a12=0,a13=0;
    float a20=0,a21=0,a22=0,a23=0, a30=0,a31=0,a32=0,a33=0;
    #pragma unroll
    for (int k = 0; k < 64; k++) {
        float4 w = *(const float4*)&Ws[k][tc];
        float x0 = Xs[tr + 0][k];
        float x1 = Xs[tr + 1][k];
        float x2 = Xs[tr + 2][k];
        float x3 = Xs[tr + 3][k];
        a00 += x0*w.x; a01 += x0*w.y; a02 += x0*w.z; a03 += x0*w.w;
        a10 += x1*w.x; a11 += x1*w.y; a12 += x1*w.z; a13 += x1*w.w;
        a20 += x2*w.x; a21 += x2*w.y; a22 += x2*w.z; a23 += x2*w.w;
        a30 += x3*w.x; a31 += x3*w.y; a32 += x3*w.z; a33 += x3*w.w;
    }
    float4 bb = make_float4(0.f, 0.f, 0.f, 0.f);
    if (bias) bb = *(const float4*)(bias + tc);
    float* y0 = Y + base + (size_t)tr * 64 + tc;
    float4 o;
    #define EMIT(r, c0, c1, c2, c3)                                        \
        o.x = c0 + bb.x; o.y = c1 + bb.y; o.z = c2 + bb.z; o.w = c3 + bb.w;\
        if (RELU) { o.x = fmaxf(o.x, 0.f); o.y = fmaxf(o.y, 0.f);          \
                    o.z = fmaxf(o.z, 0.f); o.w = fmaxf(o.w, 0.f); }        \
        *(float4*)(y0 + (r) * 64) = o;
    EMIT(0, a00, a01, a02, a03)
    EMIT(1, a10, a11, a12, a13)
    EMIT(2, a20, a21, a22, a23)
    EMIT(3, a30, a31, a32, a33)
    #undef EMIT
}

// ---- decoder: out[e] = relu(A[r]+B[c]+b1).w2 + b2 ; softplus on diag -------
#define DEC_EPW 8
__global__ void __launch_bounds__(256)
k_dec(const void* rowp, const void* colp,
      const float* __restrict__ b1, const float* __restrict__ w2,
      const float* __restrict__ b2, float* __restrict__ out, int E) {
    int is64 = g_is64;
    int gw   = (blockIdx.x * blockDim.x + threadIdx.x) >> 5;
    int lane = threadIdx.x & 31;
    int lane2 = lane * 2;
    float2 bias = *(const float2*)(b1 + lane2);
    float2 w    = *(const float2*)(w2 + lane2);
    float  bout = b2[0];
    int e0 = gw * DEC_EPW;
    if (e0 >= E) return;
    int m = E - e0; if (m > DEC_EPW) m = DEC_EPW;

    int   rr[DEC_EPW], cc[DEC_EPW];
    float s[DEC_EPW];
    #pragma unroll
    for (int j = 0; j < DEC_EPW; j++) {
        if (j < m) {
            int r = ld_idx(rowp, e0 + j, is64);
            int c = ld_idx(colp, e0 + j, is64);
            rr[j] = r; cc[j] = c;
            float2 a  = *(const float2*)(g_t0 + ((size_t)r << 6) + lane2);
            float2 bb = *(const float2*)(g_t1 + ((size_t)c << 6) + lane2);
            s[j] = fmaxf(a.x + bb.x + bias.x, 0.f) * w.x
                 + fmaxf(a.y + bb.y + bias.y, 0.f) * w.y;
        }
    }
    #pragma unroll
    for (int j = 0; j < DEC_EPW; j++) {
        if (j < m) {
            float v = s[j];
            #pragma unroll
            for (int off = 16; off; off >>= 1)
                v += __shfl_down_sync(0xffffffffu, v, off);
            if (lane == 0) {
                float val = v + bout;
                if (rr[j] == cc[j])
                    val = fmaxf(val, 0.f) + log1pf(expf(-fabsf(val)));
                out[e0 + j] = val;
            }
        }
    }
}

extern "C" void kernel_launch(void* const* d_in, const int* in_sizes, int n_in,
                              void* d_out, int out_size) {
    const float* x        = (const float*)d_in[0];
    const float* eattr    = (const float*)d_in[1];
    const float* w_enc    = (const float*)d_in[2];
    const float* b_enc    = (const float*)d_in[3];
    const float* conv1_w  = (const float*)d_in[4];
    const float* conv1_b  = (const float*)d_in[5];
    const float* conv2_w  = (const float*)d_in[6];
    const float* conv2_b  = (const float*)d_in[7];
    const float* dec_w1   = (const float*)d_in[8];
    const float* dec_b1   = (const float*)d_in[9];
    const float* dec_w2   = (const float*)d_in[10];
    const float* dec_b2   = (const float*)d_in[11];
    const void*  rowp     = d_in[12];
    const void*  colp     = d_in[13];
    float* out = (float*)d_out;

    const int N = in_sizes[0];
    const int E = in_sizes[1];

    float *p_deg, *p_h, *p_t0, *p_t1;
    int *p_cnti;
    cudaGetSymbolAddress((void**)&p_deg, g_deg);
    cudaGetSymbolAddress((void**)&p_h,   g_h);
    cudaGetSymbolAddress((void**)&p_t0,  g_t0);
    cudaGetSymbolAddress((void**)&p_t1,  g_t1);
    cudaGetSymbolAddress((void**)&p_cnti, g_cnti);

    const int TB = 256;
    int eb  = (E + TB - 1) / TB;
    int nb  = (N + TB - 1) / TB;
    int nfb = (N * L + TB - 1) / TB;
    int gb  = (N + 63) / 64;
    int ab  = (N + 7) / 8;
    int nsb = (N + 1023) / 1024;
    int db  = (int)(((long long)E + DEC_EPW * 8 - 1) / (DEC_EPW * 8));

    k_detect<<<1, 64>>>((const unsigned int*)rowp);

    k_zero2<<<nb, TB>>>(p_deg, p_cnti, N);
    k_deg_cnt<<<eb, TB>>>(eattr, colp, E);
    k_dinv<<<nb, TB>>>(N);

    k_scan1<<<nsb, 256>>>(N);
    k_scan2<<<1, 32>>>(nsb);
    k_scan3<<<nb, TB>>>(N);
    k_csr_fill<<<eb, TB>>>(eattr, rowp, colp, E);

    k_enc<<<nfb, TB>>>(x, w_enc, b_enc, N);

    // 6 GCN layers: agg (cur -> t1), gemm+bias+relu (t1 -> nxt)
    float* cur = p_h;
    float* nxt = p_t0;
    for (int i = 0; i < 3; i++) {
        k_agg<<<ab, TB>>>(cur, p_t1, N);
        k_gemm<true><<<gb, TB>>>(p_t1, conv1_w + (size_t)i * 4096,
                                 conv1_b + (size_t)i * 64, nxt);
        { float* t = cur; cur = nxt; nxt = t; }
        k_agg<<<ab, TB>>>(cur, p_t1, N);
        k_gemm<true><<<gb, TB>>>(p_t1, conv2_w + (size_t)i * 4096,
                                 conv2_b + (size_t)i * 64, nxt);
        { float* t = cur; cur = nxt; nxt = t; }
    }
    // cur == p_h after 6 layers

    k_gemm<false><<<gb, TB>>>(cur, dec_w1,        (const float*)0, p_t0);
    k_gemm<false><<<gb, TB>>>(cur, dec_w1 + 4096, (const float*)0, p_t1);
    k_dec<<<db, TB>>>(rowp, colp, dec_b1, dec_w2, dec_b2, out, E);
}

// round 8
// speedup vs baseline: 1.5969x; 1.1053x over previous
#include <cuda_runtime.h>
#include <math.h>

#define L 64
static const int NMAX = 100352;
static const int EMAX = 1605632;

__device__ __align__(16) float g_deg[NMAX];
__device__ __align__(16) float g_dinv[NMAX];
__device__ __align__(16) float g_rcp[NMAX];
__device__ __align__(16) float g_a[NMAX];     // rcp * sum(norm*x[r])
__device__ __align__(16) float g_c[NMAX];     // rcp * sum(norm)
__device__ int   g_cnti[NMAX];
__device__ int   g_offs[NMAX];
__device__ int   g_cursor[NMAX];
__device__ int   g_bsums[1024];
__device__ __align__(16) uint2 g_csr[EMAX];   // .x = row idx, .y = norm bits
__device__ __align__(16) int   g_eid[EMAX];   // original edge id per CSR slot
__device__ __align__(16) float g_u[64];
__device__ __align__(16) float g_v[64];
__device__ __align__(16) float g_h [(size_t)NMAX * L];
__device__ __align__(16) float g_t0[(size_t)NMAX * L];
__device__ __align__(16) float g_t1[(size_t)NMAX * L];
__device__ int   g_is64;

__global__ void k_detect(const unsigned int* er) {
    if (blockIdx.x == 0 && threadIdx.x == 0) {
        int ok = 1;
        #pragma unroll
        for (int i = 0; i < 64; i++)
            if (er[2 * i + 1] != 0u) ok = 0;
        g_is64 = ok;
    }
}

__device__ __forceinline__ int ld_idx(const void* p, int e, int is64) {
    if (is64) return (int)((const long long*)p)[e];
    return ((const int*)p)[e];
}

__global__ void k_zero2(float* pf, int* pi, int n) {
    int i = blockIdx.x * blockDim.x + threadIdx.x;
    if (i < n) { pf[i] = 0.0f; pi[i] = 0; }
}

__global__ void k_deg_cnt(const float* __restrict__ attr, const void* colp, int E) {
    int is64 = g_is64;
    int e = blockIdx.x * blockDim.x + threadIdx.x;
    if (e < E) {
        int c = ld_idx(colp, e, is64);
        atomicAdd(&g_deg[c], attr[e]);
        atomicAdd(&g_cnti[c], 1);
    }
}

// ---------------- prefix scan over counts -----------------------------------
__global__ void k_scan1(int N) {
    __shared__ int wsum[8];
    int t = threadIdx.x;
    int base = blockIdx.x * 1024 + t * 4;
    int v0 = 0, v1 = 0, v2 = 0, v3 = 0;
    if (base + 0 < N) v0 = g_cnti[base + 0];
    if (base + 1 < N) v1 = g_cnti[base + 1];
    if (base + 2 < N) v2 = g_cnti[base + 2];
    if (base + 3 < N) v3 = g_cnti[base + 3];
    int s = v0 + v1 + v2 + v3;
    int lane = t & 31, warp = t >> 5;
    int x = s;
    #pragma unroll
    for (int o = 1; o < 32; o <<= 1) {
        int y = __shfl_up_sync(0xffffffffu, x, o);
        if (lane >= o) x += y;
    }
    if (lane == 31) wsum[warp] = x;
    __syncthreads();
    if (warp == 0 && lane < 8) {
        int w = wsum[lane];
        #pragma unroll
        for (int o = 1; o < 8; o <<= 1) {
            int y = __shfl_up_sync(0x000000ffu, w, o);
            if (lane >= o) w += y;
        }
        wsum[lane] = w;
    }
    __syncthreads();
    int excl = x - s + (warp > 0 ? wsum[warp - 1] : 0);
    int r = excl;
    r += v0; if (base + 0 < N) g_offs[base + 0] = r;
    r += v1; if (base + 1 < N) g_offs[base + 1] = r;
    r += v2; if (base + 2 < N) g_offs[base + 2] = r;
    r += v3; if (base + 3 < N) g_offs[base + 3] = r;
    if (t == 255) g_bsums[blockIdx.x] = excl + s;
}

__global__ void k_scan2(int nb) {
    if (threadIdx.x == 0 && blockIdx.x == 0) {
        int run = 0;
        for (int i = 0; i < nb; i++) { int t = g_bsums[i]; g_bsums[i] = run; run += t; }
    }
}

// scan finalize + dinv + rcp fused
__global__ void k_scan3(int N) {
    int i = blockIdx.x * blockDim.x + threadIdx.x;
    if (i < N) {
        int cnt = g_cnti[i];
        int excl = g_offs[i] + g_bsums[i >> 10] - cnt;
        g_offs[i] = excl;
        g_cursor[i] = excl;
        float d = g_deg[i];
        g_dinv[i] = (d > 0.0f) ? rsqrtf(fmaxf(d, 1e-30f)) : 0.0f;
        g_rcp[i]  = 1.0f / fmaxf((float)cnt, 1.0f);
    }
}

// CSR fill with inline GCN norm + original edge id
__global__ void k_csr_fill(const float* __restrict__ attr, const void* rowp,
                           const void* colp, int E) {
    int is64 = g_is64;
    int e = blockIdx.x * blockDim.x + threadIdx.x;
    if (e < E) {
        int r = ld_idx(rowp, e, is64);
        int c = ld_idx(colp, e, is64);
        int p = atomicAdd(&g_cursor[c], 1);
        uint2 rec;
        rec.x = (unsigned int)r;
        rec.y = __float_as_uint(g_dinv[r] * attr[e] * g_dinv[c]);
        g_csr[p] = rec;
        g_eid[p] = e;
    }
}

// u = w_enc @ W1_0, v = b_enc @ W1_0  (one block, 64 threads)
__global__ void k_uv(const float* __restrict__ w_enc, const float* __restrict__ b_enc,
                     const float* __restrict__ W) {
    int g = threadIdx.x;
    float u = 0.f, v = 0.f;
    #pragma unroll
    for (int f = 0; f < 64; f++) {
        float wf = W[f * 64 + g];
        u += w_enc[f] * wf;
        v += b_enc[f] * wf;
    }
    g_u[g] = u;
    g_v[g] = v;
}

// layer-1 scalar sums: a[n] = rcp*sum(norm*x[r]), c[n] = rcp*sum(norm)
__global__ void __launch_bounds__(256)
k_l1sums(const float* __restrict__ x, int N) {
    int warp = threadIdx.x >> 5, lane = threadIdx.x & 31;
    int n = blockIdx.x * 8 + warp;
    if (n >= N) return;
    int st = g_offs[n];
    int en = st + g_cnti[n];
    float s1 = 0.f, s0 = 0.f;
    for (int k = st + lane; k < en; k += 32) {
        uint2 rec = g_csr[k];
        float nm = __uint_as_float(rec.y);
        s1 += nm * x[rec.x];
        s0 += nm;
    }
    #pragma unroll
    for (int off = 16; off; off >>= 1) {
        s1 += __shfl_down_sync(0xffffffffu, s1, off);
        s0 += __shfl_down_sync(0xffffffffu, s0, off);
    }
    if (lane == 0) {
        float rcp = g_rcp[n];
        g_a[n] = s1 * rcp;
        g_c[n] = s0 * rcp;
    }
}

// layer-1 output: h1[n][g] = relu(a[n]*u[g] + c[n]*v[g] + b1[g])
__global__ void k_l1out(const float* __restrict__ b1, float* __restrict__ hout, int N) {
    int i = blockIdx.x * blockDim.x + threadIdx.x;
    if (i < N * L) {
        int n = i >> 6, f = i & 63;
        float val = g_a[n] * g_u[f] + g_c[n] * g_v[f] + b1[f];
        hout[i] = fmaxf(val, 0.0f);
    }
}

// ---- aggregation: agg[n] = rcp[n] * sum_e norm_e * hin[row_e]  (warp/node) --
__global__ void __launch_bounds__(256)
k_agg(const float* __restrict__ hin, float* __restrict__ aggo, int N) {
    int warp = threadIdx.x >> 5, lane = threadIdx.x & 31;
    int n = blockIdx.x * 8 + warp;
    if (n >= N) return;
    int lane2 = lane * 2;
    int st = g_offs[n];
    int en = st + g_cnti[n];
    float ax0 = 0.f, ay0 = 0.f, ax1 = 0.f, ay1 = 0.f;
    int k = st;
    #pragma unroll 1
    for (; k + 4 <= en; k += 4) {
        uint2 e0 = g_csr[k + 0];
        uint2 e1 = g_csr[k + 1];
        uint2 e2 = g_csr[k + 2];
        uint2 e3 = g_csr[k + 3];
        float2 v0 = *(const float2*)(hin + ((size_t)e0.x << 6) + lane2);
        float2 v1 = *(const float2*)(hin + ((size_t)e1.x << 6) + lane2);
        float2 v2 = *(const float2*)(hin + ((size_t)e2.x << 6) + lane2);
        float2 v3 = *(const float2*)(hin + ((size_t)e3.x << 6) + lane2);
        float f0 = __uint_as_float(e0.y), f1 = __uint_as_float(e1.y);
        float f2 = __uint_as_float(e2.y), f3 = __uint_as_float(e3.y);
        ax0 += v0.x * f0; ay0 += v0.y * f0;
        ax1 += v1.x * f1; ay1 += v1.y * f1;
        ax0 += v2.x * f2; ay0 += v2.y * f2;
        ax1 += v3.x * f3; ay1 += v3.y * f3;
    }
    #pragma unroll 1
    for (; k < en; k++) {
        uint2 rec = g_csr[k];
        float nm = __uint_as_float(rec.y);
        float2 v = *(const float2*)(hin + ((size_t)rec.x << 6) + lane2);
        ax0 += v.x * nm; ay0 += v.y * nm;
    }
    float rcp = g_rcp[n];
    float2 o;
    o.x = (ax0 + ax1) * rcp;
    o.y = (ay0 + ay1) * rcp;
    *(float2*)(aggo + ((size_t)n << 6) + lane2) = o;
}

// ---- GEMM: Y[64 rows] = X @ W (+bias, relu). Register-blocked 4x4. ---------
template<bool RELU>
__global__ void __launch_bounds__(256)
k_gemm(const float* __restrict__ X, const float* __restrict__ W,
       const float* __restrict__ bias, float* __restrict__ Y) {
    __shared__ float Ws[64][64];
    __shared__ float Xs[64][68];
    int tid = threadIdx.x;
    const float4* W4 = (const float4*)W;
    #pragma unroll
    for (int i = 0; i < 4; i++) {
        int idx = tid + i * 256;
        float4 v = W4[idx];
        *(float4*)&Ws[idx >> 4][(idx & 15) * 4] = v;
    }
    size_t base = (size_t)blockIdx.x * (64 * 64);
    const float4* X4 = (const float4*)(X + base);
    #pragma unroll
    for (int i = 0; i < 4; i++) {
        int idx = tid + i * 256;
        float4 v = X4[idx];
        *(float4*)&Xs[idx >> 4][(idx & 15) * 4] = v;
    }
    __syncthreads();
    int tr = (tid >> 4) * 4;
    int tc = (tid & 15) * 4;
    float a00=0,a01=0,a02=0,a03=0, a10=0,a11=0,a12=0,a13=0;
    float a20=0,a21=0,a22=0,a23=0, a30=0,a31=0,a32=0,a33=0;
    #pragma unroll
    for (int k = 0; k < 64; k++) {
        float4 w = *(const float4*)&Ws[k][tc];
        float x0 = Xs[tr + 0][k];
        float x1 = Xs[tr + 1][k];
        float x2 = Xs[tr + 2][k];
        float x3 = Xs[tr + 3][k];
        a00 += x0*w.x; a01 += x0*w.y; a02 += x0*w.z; a03 += x0*w.w;
        a10 += x1*w.x; a11 += x1*w.y; a12 += x1*w.z; a13 += x1*w.w;
        a20 += x2*w.x; a21 += x2*w.y; a22 += x2*w.z; a23 += x2*w.w;
        a30 += x3*w.x; a31 += x3*w.y; a32 += x3*w.z; a33 += x3*w.w;
    }
    float4 bb = make_float4(0.f, 0.f, 0.f, 0.f);
    if (bias) bb = *(const float4*)(bias + tc);
    float* y0 = Y + base + (size_t)tr * 64 + tc;
    float4 o;
    #define EMIT(r, c0, c1, c2, c3)                                        \
        o.x = c0 + bb.x; o.y = c1 + bb.y; o.z = c2 + bb.z; o.w = c3 + bb.w;\
        if (RELU) { o.x = fmaxf(o.x, 0.f); o.y = fmaxf(o.y, 0.f);          \
                    o.z = fmaxf(o.z, 0.f); o.w = fmaxf(o.w, 0.f); }        \
        *(float4*)(y0 + (r) * 64) = o;
    EMIT(0, a00, a01, a02, a03)
    EMIT(1, a10, a11, a12, a13)
    EMIT(2, a20, a21, a22, a23)
    EMIT(3, a30, a31, a32, a33)
    #undef EMIT
}

// ---- decoder, CSR order: warp per node c; B[c] hoisted to registers --------
__global__ void __launch_bounds__(256)
k_dec_csr(const float* __restrict__ A, const float* __restrict__ B,
          const float* __restrict__ b1, const float* __restrict__ w2,
          const float* __restrict__ b2, float* __restrict__ out, int N) {
    int warp = threadIdx.x >> 5, lane = threadIdx.x & 31;
    int n = blockIdx.x * 8 + warp;
    if (n >= N) return;
    int lane2 = lane * 2;
    float2 bias = *(const float2*)(b1 + lane2);
    float2 w    = *(const float2*)(w2 + lane2);
    float  bout = b2[0];
    float2 bc   = *(const float2*)(B + ((size_t)n << 6) + lane2);
    bc.x += bias.x; bc.y += bias.y;           // fold bias into B[c]
    int st = g_offs[n];
    int en = st + g_cnti[n];
    #pragma unroll 1
    for (int k = st; k < en; k++) {
        uint2 rec = g_csr[k];
        int r = (int)rec.x;
        float2 a = *(const float2*)(A + ((size_t)r << 6) + lane2);
        float s = fmaxf(a.x + bc.x, 0.f) * w.x
                + fmaxf(a.y + bc.y, 0.f) * w.y;
        #pragma unroll
        for (int off = 16; off; off >>= 1)
            s += __shfl_down_sync(0xffffffffu, s, off);
        if (lane == 0) {
            float val = s + bout;
            if (r == n) val = fmaxf(val, 0.f) + log1pf(expf(-fabsf(val)));
            out[g_eid[k]] = val;
        }
    }
}

extern "C" void kernel_launch(void* const* d_in, const int* in_sizes, int n_in,
                              void* d_out, int out_size) {
    const float* x        = (const float*)d_in[0];
    const float* eattr    = (const float*)d_in[1];
    const float* w_enc    = (const float*)d_in[2];
    const float* b_enc    = (const float*)d_in[3];
    const float* conv1_w  = (const float*)d_in[4];
    const float* conv1_b  = (const float*)d_in[5];
    const float* conv2_w  = (const float*)d_in[6];
    const float* conv2_b  = (const float*)d_in[7];
    const float* dec_w1   = (const float*)d_in[8];
    const float* dec_b1   = (const float*)d_in[9];
    const float* dec_w2   = (const float*)d_in[10];
    const float* dec_b2   = (const float*)d_in[11];
    const void*  rowp     = d_in[12];
    const void*  colp     = d_in[13];
    float* out = (float*)d_out;

    const int N = in_sizes[0];
    const int E = in_sizes[1];

    float *p_deg, *p_h, *p_t0, *p_t1;
    int *p_cnti;
    cudaGetSymbolAddress((void**)&p_deg, g_deg);
    cudaGetSymbolAddress((void**)&p_h,   g_h);
    cudaGetSymbolAddress((void**)&p_t0,  g_t0);
    cudaGetSymbolAddress((void**)&p_t1,  g_t1);
    cudaGetSymbolAddress((void**)&p_cnti, g_cnti);

    const int TB = 256;
    int eb  = (E + TB - 1) / TB;
    int nb  = (N + TB - 1) / TB;
    int nfb = (N * L + TB - 1) / TB;
    int gb  = (N + 63) / 64;
    int ab  = (N + 7) / 8;
    int nsb = (N + 1023) / 1024;

    k_detect<<<1, 64>>>((const unsigned int*)rowp);

    k_zero2<<<nb, TB>>>(p_deg, p_cnti, N);
    k_deg_cnt<<<eb, TB>>>(eattr, colp, E);

    k_scan1<<<nsb, 256>>>(N);
    k_scan2<<<1, 32>>>(nsb);
    k_scan3<<<nb, TB>>>(N);           // offsets + cursor + dinv + rcp
    k_csr_fill<<<eb, TB>>>(eattr, rowp, colp, E);

    // layer 1 (collapsed rank-2 form), writes h1 -> g_h
    k_uv<<<1, 64>>>(w_enc, b_enc, conv1_w);
    k_l1sums<<<ab, TB>>>(x, N);
    k_l1out<<<nfb, TB>>>(conv1_b, p_h, N);

    // layers 2..6
    const float* Ws[5] = { conv2_w,            conv1_w + 4096, conv2_w + 4096,
                           conv1_w + 2*4096,   conv2_w + 2*4096 };
    const float* Bs[5] = { conv2_b,            conv1_b + 64,   conv2_b + 64,
                           conv1_b + 2*64,     conv2_b + 2*64 };
    float* cur = p_h;
    float* nxt = p_t0;
    for (int i = 0; i < 5; i++) {
        k_agg<<<ab, TB>>>(cur, p_t1, N);
        k_gemm<true><<<gb, TB>>>(p_t1, Ws[i], Bs[i], nxt);
        { float* t = cur; cur = nxt; nxt = t; }
    }
    // after 5 layers: cur == p_t0, free buffers: g_h, g_t1

    k_gemm<false><<<gb, TB>>>(cur, dec_w1,        (const float*)0, p_h);   // A
    k_gemm<false><<<gb, TB>>>(cur, dec_w1 + 4096, (const float*)0, p_t1);  // B
    k_dec_csr<<<ab, TB>>>(p_h, p_t1, dec_b1, dec_w2, dec_b2, out, N);
}

// round 9
// speedup vs baseline: 1.6206x; 1.0148x over previous
#include <cuda_runtime.h>
#include <math.h>

#define L 64
static const int NMAX = 100352;
static const int EMAX = 1605632;

__device__ __align__(16) float g_deg[NMAX];
__device__ __align__(16) float g_dinv[NMAX];
__device__ __align__(16) float g_rcp[NMAX];
__device__ __align__(16) float g_a[NMAX];
__device__ __align__(16) float g_c[NMAX];
__device__ int   g_cnti[NMAX];
__device__ int   g_offs[NMAX];
__device__ int   g_cursor[NMAX];
__device__ int   g_bsums[1024];
__device__ __align__(16) uint2 g_csr[EMAX];   // .x = row idx, .y = norm bits
__device__ __align__(16) int   g_eid[EMAX];
__device__ __align__(16) float g_u[64];
__device__ __align__(16) float g_v[64];
__device__ __align__(16) float g_h [(size_t)NMAX * L];
__device__ __align__(16) float g_t0[(size_t)NMAX * L];
__device__ __align__(16) float g_t1[(size_t)NMAX * L];
__device__ int   g_is64;

__global__ void k_detect(const unsigned int* er) {
    if (blockIdx.x == 0 && threadIdx.x == 0) {
        int ok = 1;
        #pragma unroll
        for (int i = 0; i < 64; i++)
            if (er[2 * i + 1] != 0u) ok = 0;
        g_is64 = ok;
    }
}

__device__ __forceinline__ int ld_idx(const void* p, int e, int is64) {
    if (is64) return (int)((const long long*)p)[e];
    return ((const int*)p)[e];
}

__global__ void k_zero2(float* pf, int* pi, int n) {
    int i = blockIdx.x * blockDim.x + threadIdx.x;
    if (i < n) { pf[i] = 0.0f; pi[i] = 0; }
}

__global__ void k_deg_cnt(const float* __restrict__ attr, const void* colp, int E) {
    int is64 = g_is64;
    int e = blockIdx.x * blockDim.x + threadIdx.x;
    if (e < E) {
        int c = ld_idx(colp, e, is64);
        atomicAdd(&g_deg[c], attr[e]);
        atomicAdd(&g_cnti[c], 1);
    }
}

// ---------------- prefix scan over counts -----------------------------------
__global__ void k_scan1(int N) {
    __shared__ int wsum[8];
    int t = threadIdx.x;
    int base = blockIdx.x * 1024 + t * 4;
    int v0 = 0, v1 = 0, v2 = 0, v3 = 0;
    if (base + 0 < N) v0 = g_cnti[base + 0];
    if (base + 1 < N) v1 = g_cnti[base + 1];
    if (base + 2 < N) v2 = g_cnti[base + 2];
    if (base + 3 < N) v3 = g_cnti[base + 3];
    int s = v0 + v1 + v2 + v3;
    int lane = t & 31, warp = t >> 5;
    int x = s;
    #pragma unroll
    for (int o = 1; o < 32; o <<= 1) {
        int y = __shfl_up_sync(0xffffffffu, x, o);
        if (lane >= o) x += y;
    }
    if (lane == 31) wsum[warp] = x;
    __syncthreads();
    if (warp == 0 && lane < 8) {
        int w = wsum[lane];
        #pragma unroll
        for (int o = 1; o < 8; o <<= 1) {
            int y = __shfl_up_sync(0x000000ffu, w, o);
            if (lane >= o) w += y;
        }
        wsum[lane] = w;
    }
    __syncthreads();
    int excl = x - s + (warp > 0 ? wsum[warp - 1] : 0);
    int r = excl;
    r += v0; if (base + 0 < N) g_offs[base + 0] = r;
    r += v1; if (base + 1 < N) g_offs[base + 1] = r;
    r += v2; if (base + 2 < N) g_offs[base + 2] = r;
    r += v3; if (base + 3 < N) g_offs[base + 3] = r;
    if (t == 255) g_bsums[blockIdx.x] = excl + s;
}

__global__ void k_scan2(int nb) {
    if (threadIdx.x == 0 && blockIdx.x == 0) {
        int run = 0;
        for (int i = 0; i < nb; i++) { int t = g_bsums[i]; g_bsums[i] = run; run += t; }
    }
}

__global__ void k_scan3(int N) {
    int i = blockIdx.x * blockDim.x + threadIdx.x;
    if (i < N) {
        int cnt = g_cnti[i];
        int excl = g_offs[i] + g_bsums[i >> 10] - cnt;
        g_offs[i] = excl;
        g_cursor[i] = excl;
        float d = g_deg[i];
        g_dinv[i] = (d > 0.0f) ? rsqrtf(fmaxf(d, 1e-30f)) : 0.0f;
        g_rcp[i]  = 1.0f / fmaxf((float)cnt, 1.0f);
    }
}

__global__ void k_csr_fill(const float* __restrict__ attr, const void* rowp,
                           const void* colp, int E) {
    int is64 = g_is64;
    int e = blockIdx.x * blockDim.x + threadIdx.x;
    if (e < E) {
        int r = ld_idx(rowp, e, is64);
        int c = ld_idx(colp, e, is64);
        int p = atomicAdd(&g_cursor[c], 1);
        uint2 rec;
        rec.x = (unsigned int)r;
        rec.y = __float_as_uint(g_dinv[r] * attr[e] * g_dinv[c]);
        g_csr[p] = rec;
        g_eid[p] = e;
    }
}

__global__ void k_uv(const float* __restrict__ w_enc, const float* __restrict__ b_enc,
                     const float* __restrict__ W) {
    int g = threadIdx.x;
    float u = 0.f, v = 0.f;
    #pragma unroll
    for (int f = 0; f < 64; f++) {
        float wf = W[f * 64 + g];
        u += w_enc[f] * wf;
        v += b_enc[f] * wf;
    }
    g_u[g] = u;
    g_v[g] = v;
}

__global__ void __launch_bounds__(256)
k_l1sums(const float* __restrict__ x, int N) {
    int warp = threadIdx.x >> 5, lane = threadIdx.x & 31;
    int n = blockIdx.x * 8 + warp;
    if (n >= N) return;
    int st = g_offs[n];
    int en = st + g_cnti[n];
    float s1 = 0.f, s0 = 0.f;
    for (int k = st + lane; k < en; k += 32) {
        uint2 rec = g_csr[k];
        float nm = __uint_as_float(rec.y);
        s1 += nm * x[rec.x];
        s0 += nm;
    }
    #pragma unroll
    for (int off = 16; off; off >>= 1) {
        s1 += __shfl_down_sync(0xffffffffu, s1, off);
        s0 += __shfl_down_sync(0xffffffffu, s0, off);
    }
    if (lane == 0) {
        float rcp = g_rcp[n];
        g_a[n] = s1 * rcp;
        g_c[n] = s0 * rcp;
    }
}

__global__ void k_l1out(const float* __restrict__ b1, float* __restrict__ hout, int N) {
    int i = blockIdx.x * blockDim.x + threadIdx.x;
    if (i < N * L) {
        int n = i >> 6, f = i & 63;
        float val = g_a[n] * g_u[f] + g_c[n] * g_v[f] + b1[f];
        hout[i] = fmaxf(val, 0.0f);
    }
}

// ---- aggregation (unchanged from R8) ----------------------------------------
__global__ void __launch_bounds__(256)
k_agg(const float* __restrict__ hin, float* __restrict__ aggo, int N) {
    int warp = threadIdx.x >> 5, lane = threadIdx.x & 31;
    int n = blockIdx.x * 8 + warp;
    if (n >= N) return;
    int lane2 = lane * 2;
    int st = g_offs[n];
    int en = st + g_cnti[n];
    float ax0 = 0.f, ay0 = 0.f, ax1 = 0.f, ay1 = 0.f;
    int k = st;
    #pragma unroll 1
    for (; k + 4 <= en; k += 4) {
        uint2 e0 = g_csr[k + 0];
        uint2 e1 = g_csr[k + 1];
        uint2 e2 = g_csr[k + 2];
        uint2 e3 = g_csr[k + 3];
        float2 v0 = *(const float2*)(hin + ((size_t)e0.x << 6) + lane2);
        float2 v1 = *(const float2*)(hin + ((size_t)e1.x << 6) + lane2);
        float2 v2 = *(const float2*)(hin + ((size_t)e2.x << 6) + lane2);
        float2 v3 = *(const float2*)(hin + ((size_t)e3.x << 6) + lane2);
        float f0 = __uint_as_float(e0.y), f1 = __uint_as_float(e1.y);
        float f2 = __uint_as_float(e2.y), f3 = __uint_as_float(e3.y);
        ax0 += v0.x * f0; ay0 += v0.y * f0;
        ax1 += v1.x * f1; ay1 += v1.y * f1;
        ax0 += v2.x * f2; ay0 += v2.y * f2;
        ax1 += v3.x * f3; ay1 += v3.y * f3;
    }
    #pragma unroll 1
    for (; k < en; k++) {
        uint2 rec = g_csr[k];
        float nm = __uint_as_float(rec.y);
        float2 v = *(const float2*)(hin + ((size_t)rec.x << 6) + lane2);
        ax0 += v.x * nm; ay0 += v.y * nm;
    }
    float rcp = g_rcp[n];
    float2 o;
    o.x = (ax0 + ax1) * rcp;
    o.y = (ay0 + ay1) * rcp;
    *(float2*)(aggo + ((size_t)n << 6) + lane2) = o;
}

// ---- persistent GEMM: single wave, 2 tiles/CTA, W loaded once --------------
template<bool RELU>
__global__ void __launch_bounds__(256)
k_gemm(const float* __restrict__ X, const float* __restrict__ W,
       const float* __restrict__ bias, float* __restrict__ Y, int ntiles) {
    __shared__ float Ws[64][64];
    __shared__ float Xs[64][68];
    int tid = threadIdx.x;
    const float4* W4 = (const float4*)W;
    #pragma unroll
    for (int i = 0; i < 4; i++) {
        int idx = tid + i * 256;
        float4 v = W4[idx];
        *(float4*)&Ws[idx >> 4][(idx & 15) * 4] = v;
    }
    int tr = (tid >> 4) * 4;
    int tc = (tid & 15) * 4;
    float4 bb = make_float4(0.f, 0.f, 0.f, 0.f);
    if (bias) bb = *(const float4*)(bias + tc);

    for (int t = blockIdx.x; t < ntiles; t += gridDim.x) {
        __syncthreads();   // protect Xs against readers of previous tile (and order Ws on iter 0)
        size_t base = (size_t)t * (64 * 64);
        const float4* X4 = (const float4*)(X + base);
        #pragma unroll
        for (int i = 0; i < 4; i++) {
            int idx = tid + i * 256;
            float4 v = X4[idx];
            *(float4*)&Xs[idx >> 4][(idx & 15) * 4] = v;
        }
        __syncthreads();
        float a00=0,a01=0,a02=0,a03=0, a10=0,a11=0,a12=0,a13=0;
        float a20=0,a21=0,a22=0,a23=0, a30=0,a31=0,a32=0,a33=0;
        #pragma unroll
        for (int k = 0; k < 64; k++) {
            float4 w = *(const float4*)&Ws[k][tc];
            float x0 = Xs[tr + 0][k];
            float x1 = Xs[tr + 1][k];
            float x2 = Xs[tr + 2][k];
            float x3 = Xs[tr + 3][k];
            a00 += x0*w.x; a01 += x0*w.y; a02 += x0*w.z; a03 += x0*w.w;
            a10 += x1*w.x; a11 += x1*w.y; a12 += x1*w.z; a13 += x1*w.w;
            a20 += x2*w.x; a21 += x2*w.y; a22 += x2*w.z; a23 += x2*w.w;
            a30 += x3*w.x; a31 += x3*w.y; a32 += x3*w.z; a33 += x3*w.w;
        }
        float* y0 = Y + base + (size_t)tr * 64 + tc;
        float4 o;
        #define EMIT(r, c0, c1, c2, c3)                                        \
            o.x = c0 + bb.x; o.y = c1 + bb.y; o.z = c2 + bb.z; o.w = c3 + bb.w;\
            if (RELU) { o.x = fmaxf(o.x, 0.f); o.y = fmaxf(o.y, 0.f);          \
                        o.z = fmaxf(o.z, 0.f); o.w = fmaxf(o.w, 0.f); }        \
            *(float4*)(y0 + (r) * 64) = o;
        EMIT(0, a00, a01, a02, a03)
        EMIT(1, a10, a11, a12, a13)
        EMIT(2, a20, a21, a22, a23)
        EMIT(3, a30, a31, a32, a33)
        #undef EMIT
    }
}

// ---- decoder, CSR order, 2-edge unrolled reductions -------------------------
__global__ void __launch_bounds__(256)
k_dec_csr(const float* __restrict__ A, const float* __restrict__ B,
          const float* __restrict__ b1, const float* __restrict__ w2,
          const float* __restrict__ b2, float* __restrict__ out, int N) {
    int warp = threadIdx.x >> 5, lane = threadIdx.x & 31;
    int n = blockIdx.x * 8 + warp;
    if (n >= N) return;
    int lane2 = lane * 2;
    float2 bias = *(const float2*)(b1 + lane2);
    float2 w    = *(const float2*)(w2 + lane2);
    float  bout = b2[0];
    float2 bc   = *(const float2*)(B + ((size_t)n << 6) + lane2);
    bc.x += bias.x; bc.y += bias.y;
    int st = g_offs[n];
    int en = st + g_cnti[n];
    int k = st;
    #pragma unroll 1
    for (; k + 2 <= en; k += 2) {
        uint2 rec0 = g_csr[k];
        uint2 rec1 = g_csr[k + 1];
        int r0 = (int)rec0.x, r1 = (int)rec1.x;
        float2 a0 = *(const float2*)(A + ((size_t)r0 << 6) + lane2);
        float2 a1 = *(const float2*)(A + ((size_t)r1 << 6) + lane2);
        float s0 = fmaxf(a0.x + bc.x, 0.f) * w.x + fmaxf(a0.y + bc.y, 0.f) * w.y;
        float s1 = fmaxf(a1.x + bc.x, 0.f) * w.x + fmaxf(a1.y + bc.y, 0.f) * w.y;
        #pragma unroll
        for (int off = 16; off; off >>= 1) {
            s0 += __shfl_down_sync(0xffffffffu, s0, off);
            s1 += __shfl_down_sync(0xffffffffu, s1, off);
        }
        if (lane == 0) {
            float v0 = s0 + bout;
            float v1 = s1 + bout;
            if (r0 == n) v0 = fmaxf(v0, 0.f) + log1pf(expf(-fabsf(v0)));
            if (r1 == n) v1 = fmaxf(v1, 0.f) + log1pf(expf(-fabsf(v1)));
            out[g_eid[k]]     = v0;
            out[g_eid[k + 1]] = v1;
        }
    }
    if (k < en) {
        uint2 rec = g_csr[k];
        int r = (int)rec.x;
        float2 a = *(const float2*)(A + ((size_t)r << 6) + lane2);
        float s = fmaxf(a.x + bc.x, 0.f) * w.x + fmaxf(a.y + bc.y, 0.f) * w.y;
        #pragma unroll
        for (int off = 16; off; off >>= 1)
            s += __shfl_down_sync(0xffffffffu, s, off);
        if (lane == 0) {
            float val = s + bout;
            if (r == n) val = fmaxf(val, 0.f) + log1pf(expf(-fabsf(val)));
            out[g_eid[k]] = val;
        }
    }
}

extern "C" void kernel_launch(void* const* d_in, const int* in_sizes, int n_in,
                              void* d_out, int out_size) {
    const float* x        = (const float*)d_in[0];
    const float* eattr    = (const float*)d_in[1];
    const float* w_enc    = (const float*)d_in[2];
    const float* b_enc    = (const float*)d_in[3];
    const float* conv1_w  = (const float*)d_in[4];
    const float* conv1_b  = (const float*)d_in[5];
    const float* conv2_w  = (const float*)d_in[6];
    const float* conv2_b  = (const float*)d_in[7];
    const float* dec_w1   = (const float*)d_in[8];
    const float* dec_b1   = (const float*)d_in[9];
    const float* dec_w2   = (const float*)d_in[10];
    const float* dec_b2   = (const float*)d_in[11];
    const void*  rowp     = d_in[12];
    const void*  colp     = d_in[13];
    float* out = (float*)d_out;

    const int N = in_sizes[0];
    const int E = in_sizes[1];

    float *p_deg, *p_h, *p_t0, *p_t1;
    int *p_cnti;
    cudaGetSymbolAddress((void**)&p_deg, g_deg);
    cudaGetSymbolAddress((void**)&p_h,   g_h);
    cudaGetSymbolAddress((void**)&p_t0,  g_t0);
    cudaGetSymbolAddress((void**)&p_t1,  g_t1);
    cudaGetSymbolAddress((void**)&p_cnti, g_cnti);

    const int TB = 256;
    int eb  = (E + TB - 1) / TB;
    int nb  = (N + TB - 1) / TB;
    int nfb = (N * L + TB - 1) / TB;
    int ntiles = (N + 63) / 64;
    int gg  = (ntiles + 1) / 2;       // persistent GEMM grid: 2 tiles/CTA
    int ab  = (N + 7) / 8;
    int nsb = (N + 1023) / 1024;

    k_detect<<<1, 64>>>((const unsigned int*)rowp);

    k_zero2<<<nb, TB>>>(p_deg, p_cnti, N);
    k_deg_cnt<<<eb, TB>>>(eattr, colp, E);

    k_scan1<<<nsb, 256>>>(N);
    k_scan2<<<1, 32>>>(nsb);
    k_scan3<<<nb, TB>>>(N);
    k_csr_fill<<<eb, TB>>>(eattr, rowp, colp, E);

    // layer 1 (collapsed rank-2 form)
    k_uv<<<1, 64>>>(w_enc, b_enc, conv1_w);
    k_l1sums<<<ab, TB>>>(x, N);
    k_l1out<<<nfb, TB>>>(conv1_b, p_h, N);

    // layers 2..6
    const float* Ws[5] = { conv2_w,            conv1_w + 4096, conv2_w + 4096,
                           conv1_w + 2*4096,   conv2_w + 2*4096 };
    const float* Bs[5] = { conv2_b,            conv1_b + 64,   conv2_b + 64,
                           conv1_b + 2*64,     conv2_b + 2*64 };
    float* cur = p_h;
    float* nxt = p_t0;
    for (int i = 0; i < 5; i++) {
        k_agg<<<ab, TB>>>(cur, p_t1, N);
        k_gemm<true><<<gg, TB>>>(p_t1, Ws[i], Bs[i], nxt, ntiles);
        { float* t = cur; cur = nxt; nxt = t; }
    }
    // after 5 layers: cur == p_t0, free: g_h, g_t1

    k_gemm<false><<<gg, TB>>>(cur, dec_w1,        (const float*)0, p_h,  ntiles);
    k_gemm<false><<<gg, TB>>>(cur, dec_w1 + 4096, (const float*)0, p_t1, ntiles);
    k_dec_csr<<<ab, TB>>>(p_h, p_t1, dec_b1, dec_w2, dec_b2, out, N);
}

// round 11
// speedup vs baseline: 1.6718x; 1.0316x over previous
#include <cuda_runtime.h>
#include <cuda_fp16.h>
#include <math.h>

#define L 64
static const int NMAX = 100352;
static const int EMAX = 1605632;

__device__ __align__(16) float g_deg[NMAX];
__device__ __align__(16) float g_dinv[NMAX];
__device__ __align__(16) float g_rcp[NMAX];
__device__ __align__(16) float g_a[NMAX];
__device__ __align__(16) float g_c[NMAX];
__device__ int   g_cnti[NMAX];
__device__ int   g_offs[NMAX];
__device__ int   g_cursor[NMAX];
__device__ int   g_bsums[1024];
__device__ __align__(16) uint2 g_csr[EMAX];   // .x = row idx, .y = norm bits
__device__ __align__(16) int   g_eid[EMAX];
__device__ __align__(16) float g_u[64];
__device__ __align__(16) float g_v[64];
// fp16 hidden-state ping-pong (32 half2 per row)
__device__ __align__(16) __half2 g_hh0[(size_t)NMAX * 32];
__device__ __align__(16) __half2 g_hh1[(size_t)NMAX * 32];
// fp32 scratch
__device__ __align__(16) float g_t0[(size_t)NMAX * L];
__device__ __align__(16) float g_t1[(size_t)NMAX * L];
__device__ int   g_is64;

__global__ void k_detect(const unsigned int* er) {
    if (blockIdx.x == 0 && threadIdx.x == 0) {
        int ok = 1;
        #pragma unroll
        for (int i = 0; i < 64; i++)
            if (er[2 * i + 1] != 0u) ok = 0;
        g_is64 = ok;
    }
}

__device__ __forceinline__ int ld_idx(const void* p, int e, int is64) {
    if (is64) return (int)((const long long*)p)[e];
    return ((const int*)p)[e];
}

__global__ void k_zero2(float* pf, int* pi, int n) {
    int i = blockIdx.x * blockDim.x + threadIdx.x;
    if (i < n) { pf[i] = 0.0f; pi[i] = 0; }
}

__global__ void k_deg_cnt(const float* __restrict__ attr, const void* colp, int E) {
    int is64 = g_is64;
    int e = blockIdx.x * blockDim.x + threadIdx.x;
    if (e < E) {
        int c = ld_idx(colp, e, is64);
        atomicAdd(&g_deg[c], attr[e]);
        atomicAdd(&g_cnti[c], 1);
    }
}

// ---------------- prefix scan over counts -----------------------------------
__global__ void k_scan1(int N) {
    __shared__ int wsum[8];
    int t = threadIdx.x;
    int base = blockIdx.x * 1024 + t * 4;
    int v0 = 0, v1 = 0, v2 = 0, v3 = 0;
    if (base + 0 < N) v0 = g_cnti[base + 0];
    if (base + 1 < N) v1 = g_cnti[base + 1];
    if (base + 2 < N) v2 = g_cnti[base + 2];
    if (base + 3 < N) v3 = g_cnti[base + 3];
    int s = v0 + v1 + v2 + v3;
    int lane = t & 31, warp = t >> 5;
    int x = s;
    #pragma unroll
    for (int o = 1; o < 32; o <<= 1) {
        int y = __shfl_up_sync(0xffffffffu, x, o);
        if (lane >= o) x += y;
    }
    if (lane == 31) wsum[warp] = x;
    __syncthreads();
    if (warp == 0 && lane < 8) {
        int w = wsum[lane];
        #pragma unroll
        for (int o = 1; o < 8; o <<= 1) {
            int y = __shfl_up_sync(0x000000ffu, w, o);
            if (lane >= o) w += y;
        }
        wsum[lane] = w;
    }
    __syncthreads();
    int excl = x - s + (warp > 0 ? wsum[warp - 1] : 0);
    int r = excl;
    r += v0; if (base + 0 < N) g_offs[base + 0] = r;
    r += v1; if (base + 1 < N) g_offs[base + 1] = r;
    r += v2; if (base + 2 < N) g_offs[base + 2] = r;
    r += v3; if (base + 3 < N) g_offs[base + 3] = r;
    if (t == 255) g_bsums[blockIdx.x] = excl + s;
}

__global__ void k_scan2(int nb) {
    if (threadIdx.x == 0 && blockIdx.x == 0) {
        int run = 0;
        for (int i = 0; i < nb; i++) { int t = g_bsums[i]; g_bsums[i] = run; run += t; }
    }
}

__global__ void k_scan3(int N) {
    int i = blockIdx.x * blockDim.x + threadIdx.x;
    if (i < N) {
        int cnt = g_cnti[i];
        int excl = g_offs[i] + g_bsums[i >> 10] - cnt;
        g_offs[i] = excl;
        g_cursor[i] = excl;
        float d = g_deg[i];
        g_dinv[i] = (d > 0.0f) ? rsqrtf(fmaxf(d, 1e-30f)) : 0.0f;
        g_rcp[i]  = 1.0f / fmaxf((float)cnt, 1.0f);
    }
}

__global__ void k_csr_fill(const float* __restrict__ attr, const void* rowp,
                           const void* colp, int E) {
    int is64 = g_is64;
    int e = blockIdx.x * blockDim.x + threadIdx.x;
    if (e < E) {
        int r = ld_idx(rowp, e, is64);
        int c = ld_idx(colp, e, is64);
        int p = atomicAdd(&g_cursor[c], 1);
        uint2 rec;
        rec.x = (unsigned int)r;
        rec.y = __float_as_uint(g_dinv[r] * attr[e] * g_dinv[c]);
        g_csr[p] = rec;
        g_eid[p] = e;
    }
}

__global__ void k_uv(const float* __restrict__ w_enc, const float* __restrict__ b_enc,
                     const float* __restrict__ W) {
    int g = threadIdx.x;
    float u = 0.f, v = 0.f;
    #pragma unroll
    for (int f = 0; f < 64; f++) {
        float wf = W[f * 64 + g];
        u += w_enc[f] * wf;
        v += b_enc[f] * wf;
    }
    g_u[g] = u;
    g_v[g] = v;
}

__global__ void __launch_bounds__(256)
k_l1sums(const float* __restrict__ x, int N) {
    int warp = threadIdx.x >> 5, lane = threadIdx.x & 31;
    int n = blockIdx.x * 8 + warp;
    if (n >= N) return;
    int st = g_offs[n];
    int en = st + g_cnti[n];
    float s1 = 0.f, s0 = 0.f;
    for (int k = st + lane; k < en; k += 32) {
        uint2 rec = g_csr[k];
        float nm = __uint_as_float(rec.y);
        s1 += nm * x[rec.x];
        s0 += nm;
    }
    #pragma unroll
    for (int off = 16; off; off >>= 1) {
        s1 += __shfl_down_sync(0xffffffffu, s1, off);
        s0 += __shfl_down_sync(0xffffffffu, s0, off);
    }
    if (lane == 0) {
        float rcp = g_rcp[n];
        g_a[n] = s1 * rcp;
        g_c[n] = s0 * rcp;
    }
}

// layer-1 output -> half2
__global__ void k_l1out(const float* __restrict__ b1, __half2* __restrict__ hout, int N) {
    int i = blockIdx.x * blockDim.x + threadIdx.x;   // over N*32 half2
    if (i < N * 32) {
        int n = i >> 5, f2 = (i & 31) * 2;
        float an = g_a[n], cn = g_c[n];
        float v0 = fmaxf(an * g_u[f2]     + cn * g_v[f2]     + b1[f2],     0.f);
        float v1 = fmaxf(an * g_u[f2 + 1] + cn * g_v[f2 + 1] + b1[f2 + 1], 0.f);
        hout[i] = __floats2half2_rn(v0, v1);
    }
}

// ---- aggregation over fp16 h ------------------------------------------------
__global__ void __launch_bounds__(256)
k_agg(const __half2* __restrict__ hin, float* __restrict__ aggo, int N) {
    int warp = threadIdx.x >> 5, lane = threadIdx.x & 31;
    int n = blockIdx.x * 8 + warp;
    if (n >= N) return;
    int st = g_offs[n];
    int en = st + g_cnti[n];
    float ax0 = 0.f, ay0 = 0.f, ax1 = 0.f, ay1 = 0.f;
    int k = st;
    #pragma unroll 1
    for (; k + 4 <= en; k += 4) {
        uint2 e0 = g_csr[k + 0];
        uint2 e1 = g_csr[k + 1];
        uint2 e2 = g_csr[k + 2];
        uint2 e3 = g_csr[k + 3];
        float2 v0 = __half22float2(hin[((size_t)e0.x << 5) + lane]);
        float2 v1 = __half22float2(hin[((size_t)e1.x << 5) + lane]);
        float2 v2 = __half22float2(hin[((size_t)e2.x << 5) + lane]);
        float2 v3 = __half22float2(hin[((size_t)e3.x << 5) + lane]);
        float f0 = __uint_as_float(e0.y), f1 = __uint_as_float(e1.y);
        float f2 = __uint_as_float(e2.y), f3 = __uint_as_float(e3.y);
        ax0 += v0.x * f0; ay0 += v0.y * f0;
        ax1 += v1.x * f1; ay1 += v1.y * f1;
        ax0 += v2.x * f2; ay0 += v2.y * f2;
        ax1 += v3.x * f3; ay1 += v3.y * f3;
    }
    #pragma unroll 1
    for (; k < en; k++) {
        uint2 rec = g_csr[k];
        float nm = __uint_as_float(rec.y);
        float2 v = __half22float2(hin[((size_t)rec.x << 5) + lane]);
        ax0 += v.x * nm; ay0 += v.y * nm;
    }
    float rcp = g_rcp[n];
    float2 o;
    o.x = (ax0 + ax1) * rcp;
    o.y = (ay0 + ay1) * rcp;
    *(float2*)(aggo + ((size_t)n << 6) + lane * 2) = o;
}

// ---- persistent GEMM, fp32 in -> fp16 out (+bias, relu) ---------------------
__global__ void __launch_bounds__(256)
k_gemm_f2h(const float* __restrict__ X, const float* __restrict__ W,
           const float* __restrict__ bias, __half2* __restrict__ Y, int ntiles) {
    __shared__ float Ws[64][64];
    __shared__ float Xs[64][68];
    int tid = threadIdx.x;
    const float4* W4 = (const float4*)W;
    #pragma unroll
    for (int i = 0; i < 4; i++) {
        int idx = tid + i * 256;
        float4 v = W4[idx];
        *(float4*)&Ws[idx >> 4][(idx & 15) * 4] = v;
    }
    int tr = (tid >> 4) * 4;
    int tc = (tid & 15) * 4;
    float4 bb = *(const float4*)(bias + tc);

    for (int t = blockIdx.x; t < ntiles; t += gridDim.x) {
        __syncthreads();
        size_t base = (size_t)t * (64 * 64);
        const float4* X4 = (const float4*)(X + base);
        #pragma unroll
        for (int i = 0; i < 4; i++) {
            int idx = tid + i * 256;
            float4 v = X4[idx];
            *(float4*)&Xs[idx >> 4][(idx & 15) * 4] = v;
        }
        __syncthreads();
        float a00=0,a01=0,a02=0,a03=0, a10=0,a11=0,a12=0,a13=0;
        float a20=0,a21=0,a22=0,a23=0, a30=0,a31=0,a32=0,a33=0;
        #pragma unroll
        for (int k = 0; k < 64; k++) {
            float4 w = *(const float4*)&Ws[k][tc];
            float x0 = Xs[tr + 0][k];
            float x1 = Xs[tr + 1][k];
            float x2 = Xs[tr + 2][k];
            float x3 = Xs[tr + 3][k];
            a00 += x0*w.x; a01 += x0*w.y; a02 += x0*w.z; a03 += x0*w.w;
            a10 += x1*w.x; a11 += x1*w.y; a12 += x1*w.z; a13 += x1*w.w;
            a20 += x2*w.x; a21 += x2*w.y; a22 += x2*w.z; a23 += x2*w.w;
            a30 += x3*w.x; a31 += x3*w.y; a32 += x3*w.z; a33 += x3*w.w;
        }
        size_t hbase = (size_t)t * (64 * 32) + (size_t)tr * 32 + (tc >> 1);
        #define EMITH(r, c0, c1, c2, c3) {                                     \
            float o0 = fmaxf(c0 + bb.x, 0.f), o1 = fmaxf(c1 + bb.y, 0.f);      \
            float o2 = fmaxf(c2 + bb.z, 0.f), o3 = fmaxf(c3 + bb.w, 0.f);      \
            __half2 h0 = __floats2half2_rn(o0, o1);                            \
            __half2 h1 = __floats2half2_rn(o2, o3);                            \
            *(uint2*)(Y + hbase + (size_t)(r) * 32) =                          \
                make_uint2(*(unsigned*)&h0, *(unsigned*)&h1); }
        EMITH(0, a00, a01, a02, a03)
        EMITH(1, a10, a11, a12, a13)
        EMITH(2, a20, a21, a22, a23)
        EMITH(3, a30, a31, a32, a33)
        #undef EMITH
    }
}

// ---- persistent GEMM, fp16 in -> fp32 out (decoder halves) ------------------
// Per tile: 64 rows x 64 halves = 8192 B = 512 uint4. One uint4 = 8 halves
// = 4 half2 = 8 columns. Row = idx>>3, col0 = (idx&7)*8.
__global__ void __launch_bounds__(256)
k_gemm_h2f(const __half2* __restrict__ X, const float* __restrict__ W,
           float* __restrict__ Y, int ntiles) {
    __shared__ float Ws[64][64];
    __shared__ float Xs[64][68];
    int tid = threadIdx.x;
    const float4* W4 = (const float4*)W;
    #pragma unroll
    for (int i = 0; i < 4; i++) {
        int idx = tid + i * 256;
        float4 v = W4[idx];
        *(float4*)&Ws[idx >> 4][(idx & 15) * 4] = v;
    }
    int tr = (tid >> 4) * 4;
    int tc = (tid & 15) * 4;

    for (int t = blockIdx.x; t < ntiles; t += gridDim.x) {
        __syncthreads();
        size_t hbase = (size_t)t * (64 * 32);       // in half2 units
        const uint4* X4 = (const uint4*)(X + hbase);
        #pragma unroll
        for (int i = 0; i < 2; i++) {
            int idx = tid + i * 256;                // 0..511
            uint4 v = X4[idx];
            int row = idx >> 3;                     // 8 uint4 per 64-half row
            int c0  = (idx & 7) * 8;                // 8 columns per uint4
            float2 f0 = __half22float2(*(__half2*)&v.x);
            float2 f1 = __half22float2(*(__half2*)&v.y);
            float2 f2 = __half22float2(*(__half2*)&v.z);
            float2 f3 = __half22float2(*(__half2*)&v.w);
            Xs[row][c0 + 0] = f0.x; Xs[row][c0 + 1] = f0.y;
            Xs[row][c0 + 2] = f1.x; Xs[row][c0 + 3] = f1.y;
            Xs[row][c0 + 4] = f2.x; Xs[row][c0 + 5] = f2.y;
            Xs[row][c0 + 6] = f3.x; Xs[row][c0 + 7] = f3.y;
        }
        __syncthreads();
        float a00=0,a01=0,a02=0,a03=0, a10=0,a11=0,a12=0,a13=0;
        float a20=0,a21=0,a22=0,a23=0, a30=0,a31=0,a32=0,a33=0;
        #pragma unroll
        for (int k = 0; k < 64; k++) {
            float4 w = *(const float4*)&Ws[k][tc];
            float x0 = Xs[tr + 0][k];
            float x1 = Xs[tr + 1][k];
            float x2 = Xs[tr + 2][k];
            float x3 = Xs[tr + 3][k];
            a00 += x0*w.x; a01 += x0*w.y; a02 += x0*w.z; a03 += x0*w.w;
            a10 += x1*w.x; a11 += x1*w.y; a12 += x1*w.z; a13 += x1*w.w;
            a20 += x2*w.x; a21 += x2*w.y; a22 += x2*w.z; a23 += x2*w.w;
            a30 += x3*w.x; a31 += x3*w.y; a32 += x3*w.z; a33 += x3*w.w;
        }
        size_t base = (size_t)t * (64 * 64);
        float* y0 = Y + base + (size_t)tr * 64 + tc;
        *(float4*)(y0 + 0*64) = make_float4(a00, a01, a02, a03);
        *(float4*)(y0 + 1*64) = make_float4(a10, a11, a12, a13);
        *(float4*)(y0 + 2*64) = make_float4(a20, a21, a22, a23);
        *(float4*)(y0 + 3*64) = make_float4(a30, a31, a32, a33);
    }
}

// ---- decoder, CSR order, 2-edge unrolled ------------------------------------
__global__ void __launch_bounds__(256)
k_dec_csr(const float* __restrict__ A, const float* __restrict__ B,
          const float* __restrict__ b1, const float* __restrict__ w2,
          const float* __restrict__ b2, float* __restrict__ out, int N) {
    int warp = threadIdx.x >> 5, lane = threadIdx.x & 31;
    int n = blockIdx.x * 8 + warp;
    if (n >= N) return;
    int lane2 = lane * 2;
    float2 bias = *(const float2*)(b1 + lane2);
    float2 w    = *(const float2*)(w2 + lane2);
    float  bout = b2[0];
    float2 bc   = *(const float2*)(B + ((size_t)n << 6) + lane2);
    bc.x += bias.x; bc.y += bias.y;
    int st = g_offs[n];
    int en = st + g_cnti[n];
    int k = st;
    #pragma unroll 1
    for (; k + 2 <= en; k += 2) {
        uint2 rec0 = g_csr[k];
        uint2 rec1 = g_csr[k + 1];
        int r0 = (int)rec0.x, r1 = (int)rec1.x;
        float2 a0 = *(const float2*)(A + ((size_t)r0 << 6) + lane2);
        float2 a1 = *(const float2*)(A + ((size_t)r1 << 6) + lane2);
        float s0 = fmaxf(a0.x + bc.x, 0.f) * w.x + fmaxf(a0.y + bc.y, 0.f) * w.y;
        float s1 = fmaxf(a1.x + bc.x, 0.f) * w.x + fmaxf(a1.y + bc.y, 0.f) * w.y;
        #pragma unroll
        for (int off = 16; off; off >>= 1) {
            s0 += __shfl_down_sync(0xffffffffu, s0, off);
            s1 += __shfl_down_sync(0xffffffffu, s1, off);
        }
        if (lane == 0) {
            float v0 = s0 + bout;
            float v1 = s1 + bout;
            if (r0 == n) v0 = fmaxf(v0, 0.f) + log1pf(expf(-fabsf(v0)));
            if (r1 == n) v1 = fmaxf(v1, 0.f) + log1pf(expf(-fabsf(v1)));
            out[g_eid[k]]     = v0;
            out[g_eid[k + 1]] = v1;
        }
    }
    if (k < en) {
        uint2 rec = g_csr[k];
        int r = (int)rec.x;
        float2 a = *(const float2*)(A + ((size_t)r << 6) + lane2);
        float s = fmaxf(a.x + bc.x, 0.f) * w.x + fmaxf(a.y + bc.y, 0.f) * w.y;
        #pragma unroll
        for (int off = 16; off; off >>= 1)
            s += __shfl_down_sync(0xffffffffu, s, off);
        if (lane == 0) {
            float val = s + bout;
            if (r == n) val = fmaxf(val, 0.f) + log1pf(expf(-fabsf(val)));
            out[g_eid[k]] = val;
        }
    }
}

extern "C" void kernel_launch(void* const* d_in, const int* in_sizes, int n_in,
                              void* d_out, int out_size) {
    const float* x        = (const float*)d_in[0];
    const float* eattr    = (const float*)d_in[1];
    const float* w_enc    = (const float*)d_in[2];
    const float* b_enc    = (const float*)d_in[3];
    const float* conv1_w  = (const float*)d_in[4];
    const float* conv1_b  = (const float*)d_in[5];
    const float* conv2_w  = (const float*)d_in[6];
    const float* conv2_b  = (const float*)d_in[7];
    const float* dec_w1   = (const float*)d_in[8];
    const float* dec_b1   = (const float*)d_in[9];
    const float* dec_w2   = (const float*)d_in[10];
    const float* dec_b2   = (const float*)d_in[11];
    const void*  rowp     = d_in[12];
    const void*  colp     = d_in[13];
    float* out = (float*)d_out;

    const int N = in_sizes[0];
    const int E = in_sizes[1];

    float *p_deg, *p_t0, *p_t1;
    int *p_cnti;
    __half2 *p_hh0, *p_hh1;
    cudaGetSymbolAddress((void**)&p_deg, g_deg);
    cudaGetSymbolAddress((void**)&p_t0,  g_t0);
    cudaGetSymbolAddress((void**)&p_t1,  g_t1);
    cudaGetSymbolAddress((void**)&p_cnti, g_cnti);
    cudaGetSymbolAddress((void**)&p_hh0, g_hh0);
    cudaGetSymbolAddress((void**)&p_hh1, g_hh1);

    const int TB = 256;
    int eb  = (E + TB - 1) / TB;
    int nb  = (N + TB - 1) / TB;
    int nhb = (N * 32 + TB - 1) / TB;
    int ntiles = (N + 63) / 64;
    int gg  = (ntiles + 1) / 2;
    int ab  = (N + 7) / 8;
    int nsb = (N + 1023) / 1024;

    k_detect<<<1, 64>>>((const unsigned int*)rowp);

    k_zero2<<<nb, TB>>>(p_deg, p_cnti, N);
    k_deg_cnt<<<eb, TB>>>(eattr, colp, E);

    k_scan1<<<nsb, 256>>>(N);
    k_scan2<<<1, 32>>>(nsb);
    k_scan3<<<nb, TB>>>(N);
    k_csr_fill<<<eb, TB>>>(eattr, rowp, colp, E);

    // layer 1 (collapsed rank-2 form) -> hh0 (fp16)
    k_uv<<<1, 64>>>(w_enc, b_enc, conv1_w);
    k_l1sums<<<ab, TB>>>(x, N);
    k_l1out<<<nhb, TB>>>(conv1_b, p_hh0, N);

    // layers 2..6: agg(fp16 h -> fp32 t1), gemm(f32 -> fp16 h)
    const float* Ws[5] = { conv2_w,            conv1_w + 4096, conv2_w + 4096,
                           conv1_w + 2*4096,   conv2_w + 2*4096 };
    const float* Bs[5] = { conv2_b,            conv1_b + 64,   conv2_b + 64,
                           conv1_b + 2*64,     conv2_b + 2*64 };
    __half2* cur = p_hh0;
    __half2* nxt = p_hh1;
    for (int i = 0; i < 5; i++) {
        k_agg<<<ab, TB>>>(cur, p_t1, N);
        k_gemm_f2h<<<gg, TB>>>(p_t1, Ws[i], Bs[i], nxt, ntiles);
        { __half2* t = cur; cur = nxt; nxt = t; }
    }

    // decoder halves: A = h6 @ W1_top -> t0 ; B = h6 @ W1_bot -> t1
    k_gemm_h2f<<<gg, TB>>>(cur, dec_w1,        p_t0, ntiles);
    k_gemm_h2f<<<gg, TB>>>(cur, dec_w1 + 4096, p_t1, ntiles);
    k_dec_csr<<<ab, TB>>>(p_t0, p_t1, dec_b1, dec_w2, dec_b2, out, N);
}

// round 12
// speedup vs baseline: 1.6837x; 1.0071x over previous
#include <cuda_runtime.h>
#include <cuda_fp16.h>
#include <math.h>

#define L 64
static const int NMAX = 100352;
static const int EMAX = 1605632;

__device__ __align__(16) float g_deg[NMAX];
__device__ __align__(16) float g_dinv[NMAX];
__device__ __align__(16) float g_rcp[NMAX];
__device__ __align__(16) float g_a[NMAX];
__device__ __align__(16) float g_c[NMAX];
__device__ int   g_cnti[NMAX];
__device__ int   g_offs[NMAX];
__device__ int   g_cursor[NMAX];
__device__ int   g_bsums[1024];
__device__ __align__(16) uint2 g_csr[EMAX];   // .x = row idx, .y = norm bits
__device__ __align__(16) int   g_eid[EMAX];
__device__ __align__(16) float g_u[64];
__device__ __align__(16) float g_v[64];
__device__ __align__(16) __half2 g_hh0[(size_t)NMAX * 32];
__device__ __align__(16) __half2 g_hh1[(size_t)NMAX * 32];
__device__ __align__(16) float g_t0[(size_t)NMAX * L];
__device__ __align__(16) float g_t1[(size_t)NMAX * L];
__device__ int   g_is64;

__global__ void k_detect(const unsigned int* er) {
    if (blockIdx.x == 0 && threadIdx.x == 0) {
        int ok = 1;
        #pragma unroll
        for (int i = 0; i < 64; i++)
            if (er[2 * i + 1] != 0u) ok = 0;
        g_is64 = ok;
    }
}

__device__ __forceinline__ int ld_idx(const void* p, int e, int is64) {
    if (is64) return (int)((const long long*)p)[e];
    return ((const int*)p)[e];
}

__global__ void k_zero2(float* pf, int* pi, int n) {
    int i = blockIdx.x * blockDim.x + threadIdx.x;
    if (i < n) { pf[i] = 0.0f; pi[i] = 0; }
}

__global__ void k_deg_cnt(const float* __restrict__ attr, const void* colp, int E) {
    int is64 = g_is64;
    int e = blockIdx.x * blockDim.x + threadIdx.x;
    if (e < E) {
        int c = ld_idx(colp, e, is64);
        atomicAdd(&g_deg[c], attr[e]);
        atomicAdd(&g_cnti[c], 1);
    }
}

// ---------------- prefix scan over counts -----------------------------------
__global__ void k_scan1(int N) {
    __shared__ int wsum[8];
    int t = threadIdx.x;
    int base = blockIdx.x * 1024 + t * 4;
    int v0 = 0, v1 = 0, v2 = 0, v3 = 0;
    if (base + 0 < N) v0 = g_cnti[base + 0];
    if (base + 1 < N) v1 = g_cnti[base + 1];
    if (base + 2 < N) v2 = g_cnti[base + 2];
    if (base + 3 < N) v3 = g_cnti[base + 3];
    int s = v0 + v1 + v2 + v3;
    int lane = t & 31, warp = t >> 5;
    int x = s;
    #pragma unroll
    for (int o = 1; o < 32; o <<= 1) {
        int y = __shfl_up_sync(0xffffffffu, x, o);
        if (lane >= o) x += y;
    }
    if (lane == 31) wsum[warp] = x;
    __syncthreads();
    if (warp == 0 && lane < 8) {
        int w = wsum[lane];
        #pragma unroll
        for (int o = 1; o < 8; o <<= 1) {
            int y = __shfl_up_sync(0x000000ffu, w, o);
            if (lane >= o) w += y;
        }
        wsum[lane] = w;
    }
    __syncthreads();
    int excl = x - s + (warp > 0 ? wsum[warp - 1] : 0);
    int r = excl;
    r += v0; if (base + 0 < N) g_offs[base + 0] = r;
    r += v1; if (base + 1 < N) g_offs[base + 1] = r;
    r += v2; if (base + 2 < N) g_offs[base + 2] = r;
    r += v3; if (base + 3 < N) g_offs[base + 3] = r;
    if (t == 255) g_bsums[blockIdx.x] = excl + s;
}

__global__ void k_scan2(int nb) {
    if (threadIdx.x == 0 && blockIdx.x == 0) {
        int run = 0;
        for (int i = 0; i < nb; i++) { int t = g_bsums[i]; g_bsums[i] = run; run += t; }
    }
}

__global__ void k_scan3(int N) {
    int i = blockIdx.x * blockDim.x + threadIdx.x;
    if (i < N) {
        int cnt = g_cnti[i];
        int excl = g_offs[i] + g_bsums[i >> 10] - cnt;
        g_offs[i] = excl;
        g_cursor[i] = excl;
        float d = g_deg[i];
        g_dinv[i] = (d > 0.0f) ? rsqrtf(fmaxf(d, 1e-30f)) : 0.0f;
        g_rcp[i]  = 1.0f / fmaxf((float)cnt, 1.0f);
    }
}

__global__ void k_csr_fill(const float* __restrict__ attr, const void* rowp,
                           const void* colp, int E) {
    int is64 = g_is64;
    int e = blockIdx.x * blockDim.x + threadIdx.x;
    if (e < E) {
        int r = ld_idx(rowp, e, is64);
        int c = ld_idx(colp, e, is64);
        int p = atomicAdd(&g_cursor[c], 1);
        uint2 rec;
        rec.x = (unsigned int)r;
        rec.y = __float_as_uint(g_dinv[r] * attr[e] * g_dinv[c]);
        g_csr[p] = rec;
        g_eid[p] = e;
    }
}

__global__ void k_uv(const float* __restrict__ w_enc, const float* __restrict__ b_enc,
                     const float* __restrict__ W) {
    int g = threadIdx.x;
    float u = 0.f, v = 0.f;
    #pragma unroll
    for (int f = 0; f < 64; f++) {
        float wf = W[f * 64 + g];
        u += w_enc[f] * wf;
        v += b_enc[f] * wf;
    }
    g_u[g] = u;
    g_v[g] = v;
}

__global__ void __launch_bounds__(256)
k_l1sums(const float* __restrict__ x, int N) {
    int warp = threadIdx.x >> 5, lane = threadIdx.x & 31;
    int n = blockIdx.x * 8 + warp;
    if (n >= N) return;
    int st = g_offs[n];
    int en = st + g_cnti[n];
    float s1 = 0.f, s0 = 0.f;
    for (int k = st + lane; k < en; k += 32) {
        uint2 rec = g_csr[k];
        float nm = __uint_as_float(rec.y);
        s1 += nm * x[rec.x];
        s0 += nm;
    }
    #pragma unroll
    for (int off = 16; off; off >>= 1) {
        s1 += __shfl_down_sync(0xffffffffu, s1, off);
        s0 += __shfl_down_sync(0xffffffffu, s0, off);
    }
    if (lane == 0) {
        float rcp = g_rcp[n];
        g_a[n] = s1 * rcp;
        g_c[n] = s0 * rcp;
    }
}

__global__ void k_l1out(const float* __restrict__ b1, __half2* __restrict__ hout, int N) {
    int i = blockIdx.x * blockDim.x + threadIdx.x;   // over N*32 half2
    if (i < N * 32) {
        int n = i >> 5, f2 = (i & 31) * 2;
        float an = g_a[n], cn = g_c[n];
        float v0 = fmaxf(an * g_u[f2]     + cn * g_v[f2]     + b1[f2],     0.f);
        float v1 = fmaxf(an * g_u[f2 + 1] + cn * g_v[f2 + 1] + b1[f2 + 1], 0.f);
        hout[i] = __floats2half2_rn(v0, v1);
    }
}

// ---- aggregation over fp16 h: 4 edges/warp-iteration, uint4 loads ----------
// Warp per node. 4 groups x 8 lanes; group g handles edge k+g; lane loads
// uint4 = 8 halves = features sl*8..sl*8+7. Cross-group shfl_xor combine at end.
__global__ void __launch_bounds__(256)
k_agg(const __half2* __restrict__ hin, float* __restrict__ aggo, int N) {
    int warp = threadIdx.x >> 5, lane = threadIdx.x & 31;
    int n = blockIdx.x * 8 + warp;
    if (n >= N) return;
    int g  = lane >> 3;     // edge group 0..3
    int sl = lane & 7;      // sub-lane: feature chunk
    int st = g_offs[n];
    int en = st + g_cnti[n];
    float2 a0 = make_float2(0.f, 0.f), a1 = a0, a2 = a0, a3 = a0;
    #pragma unroll 1
    for (int k = st; k < en; k += 4) {
        int e = k + g;
        int ec = e < en - 1 ? e : en - 1;       // clamp (cnt >= 1 always: self-loops)
        uint2 rec = g_csr[ec];
        float nm = (e < en) ? __uint_as_float(rec.y) : 0.f;
        const uint4 v = ((const uint4*)(hin + ((size_t)rec.x << 5)))[sl];
        float2 f0 = __half22float2(*(const __half2*)&v.x);
        float2 f1 = __half22float2(*(const __half2*)&v.y);
        float2 f2 = __half22float2(*(const __half2*)&v.z);
        float2 f3 = __half22float2(*(const __half2*)&v.w);
        a0.x += f0.x * nm; a0.y += f0.y * nm;
        a1.x += f1.x * nm; a1.y += f1.y * nm;
        a2.x += f2.x * nm; a2.y += f2.y * nm;
        a3.x += f3.x * nm; a3.y += f3.y * nm;
    }
    // combine across the 4 groups (lanes l, l+8, l+16, l+24)
    #pragma unroll
    for (int off = 8; off <= 16; off <<= 1) {
        a0.x += __shfl_xor_sync(0xffffffffu, a0.x, off);
        a0.y += __shfl_xor_sync(0xffffffffu, a0.y, off);
        a1.x += __shfl_xor_sync(0xffffffffu, a1.x, off);
        a1.y += __shfl_xor_sync(0xffffffffu, a1.y, off);
        a2.x += __shfl_xor_sync(0xffffffffu, a2.x, off);
        a2.y += __shfl_xor_sync(0xffffffffu, a2.y, off);
        a3.x += __shfl_xor_sync(0xffffffffu, a3.x, off);
        a3.y += __shfl_xor_sync(0xffffffffu, a3.y, off);
    }
    if (lane < 8) {
        float rcp = g_rcp[n];
        float4 oA = make_float4(a0.x * rcp, a0.y * rcp, a1.x * rcp, a1.y * rcp);
        float4 oB = make_float4(a2.x * rcp, a2.y * rcp, a3.x * rcp, a3.y * rcp);
        float* y = aggo + ((size_t)n << 6) + sl * 8;
        *(float4*)(y + 0) = oA;
        *(float4*)(y + 4) = oB;
    }
}

// ---- persistent GEMM, fp32 in -> fp16 out (+bias, relu) ---------------------
__global__ void __launch_bounds__(256)
k_gemm_f2h(const float* __restrict__ X, const float* __restrict__ W,
           const float* __restrict__ bias, __half2* __restrict__ Y, int ntiles) {
    __shared__ float Ws[64][64];
    __shared__ float Xs[64][68];
    int tid = threadIdx.x;
    const float4* W4 = (const float4*)W;
    #pragma unroll
    for (int i = 0; i < 4; i++) {
        int idx = tid + i * 256;
        float4 v = W4[idx];
        *(float4*)&Ws[idx >> 4][(idx & 15) * 4] = v;
    }
    int tr = (tid >> 4) * 4;
    int tc = (tid & 15) * 4;
    float4 bb = *(const float4*)(bias + tc);

    for (int t = blockIdx.x; t < ntiles; t += gridDim.x) {
        __syncthreads();
        size_t base = (size_t)t * (64 * 64);
        const float4* X4 = (const float4*)(X + base);
        #pragma unroll
        for (int i = 0; i < 4; i++) {
            int idx = tid + i * 256;
            float4 v = X4[idx];
            *(float4*)&Xs[idx >> 4][(idx & 15) * 4] = v;
        }
        __syncthreads();
        float a00=0,a01=0,a02=0,a03=0, a10=0,a11=0,a12=0,a13=0;
        float a20=0,a21=0,a22=0,a23=0, a30=0,a31=0,a32=0,a33=0;
        #pragma unroll
        for (int k = 0; k < 64; k++) {
            float4 w = *(const float4*)&Ws[k][tc];
            float x0 = Xs[tr + 0][k];
            float x1 = Xs[tr + 1][k];
            float x2 = Xs[tr + 2][k];
            float x3 = Xs[tr + 3][k];
            a00 += x0*w.x; a01 += x0*w.y; a02 += x0*w.z; a03 += x0*w.w;
            a10 += x1*w.x; a11 += x1*w.y; a12 += x1*w.z; a13 += x1*w.w;
            a20 += x2*w.x; a21 += x2*w.y; a22 += x2*w.z; a23 += x2*w.w;
            a30 += x3*w.x; a31 += x3*w.y; a32 += x3*w.z; a33 += x3*w.w;
        }
        size_t hbase = (size_t)t * (64 * 32) + (size_t)tr * 32 + (tc >> 1);
        #define EMITH(r, c0, c1, c2, c3) {                                     \
            float o0 = fmaxf(c0 + bb.x, 0.f), o1 = fmaxf(c1 + bb.y, 0.f);      \
            float o2 = fmaxf(c2 + bb.z, 0.f), o3 = fmaxf(c3 + bb.w, 0.f);      \
            __half2 h0 = __floats2half2_rn(o0, o1);                            \
            __half2 h1 = __floats2half2_rn(o2, o3);                            \
            *(uint2*)(Y + hbase + (size_t)(r) * 32) =                          \
                make_uint2(*(unsigned*)&h0, *(unsigned*)&h1); }
        EMITH(0, a00, a01, a02, a03)
        EMITH(1, a10, a11, a12, a13)
        EMITH(2, a20, a21, a22, a23)
        EMITH(3, a30, a31, a32, a33)
        #undef EMITH
    }
}

// ---- persistent GEMM, fp16 in -> fp32 out (decoder halves) ------------------
__global__ void __launch_bounds__(256)
k_gemm_h2f(const __half2* __restrict__ X, const float* __restrict__ W,
           float* __restrict__ Y, int ntiles) {
    __shared__ float Ws[64][64];
    __shared__ float Xs[64][68];
    int tid = threadIdx.x;
    const float4* W4 = (const float4*)W;
    #pragma unroll
    for (int i = 0; i < 4; i++) {
        int idx = tid + i * 256;
        float4 v = W4[idx];
        *(float4*)&Ws[idx >> 4][(idx & 15) * 4] = v;
    }
    int tr = (tid >> 4) * 4;
    int tc = (tid & 15) * 4;

    for (int t = blockIdx.x; t < ntiles; t += gridDim.x) {
        __syncthreads();
        size_t hbase = (size_t)t * (64 * 32);
        const uint4* X4 = (const uint4*)(X + hbase);
        #pragma unroll
        for (int i = 0; i < 2; i++) {
            int idx = tid + i * 256;                // 0..511
            uint4 v = X4[idx];
            int row = idx >> 3;
            int c0  = (idx & 7) * 8;
            float2 f0 = __half22float2(*(__half2*)&v.x);
            float2 f1 = __half22float2(*(__half2*)&v.y);
            float2 f2 = __half22float2(*(__half2*)&v.z);
            float2 f3 = __half22float2(*(__half2*)&v.w);
            Xs[row][c0 + 0] = f0.x; Xs[row][c0 + 1] = f0.y;
            Xs[row][c0 + 2] = f1.x; Xs[row][c0 + 3] = f1.y;
            Xs[row][c0 + 4] = f2.x; Xs[row][c0 + 5] = f2.y;
            Xs[row][c0 + 6] = f3.x; Xs[row][c0 + 7] = f3.y;
        }
        __syncthreads();
        float a00=0,a01=0,a02=0,a03=0, a10=0,a11=0,a12=0,a13=0;
        float a20=0,a21=0,a22=0,a23=0, a30=0,a31=0,a32=0,a33=0;
        #pragma unroll
        for (int k = 0; k < 64; k++) {
            float4 w = *(const float4*)&Ws[k][tc];
            float x0 = Xs[tr + 0][k];
            float x1 = Xs[tr + 1][k];
            float x2 = Xs[tr + 2][k];
            float x3 = Xs[tr + 3][k];
            a00 += x0*w.x; a01 += x0*w.y; a02 += x0*w.z; a03 += x0*w.w;
            a10 += x1*w.x; a11 += x1*w.y; a12 += x1*w.z; a13 += x1*w.w;
            a20 += x2*w.x; a21 += x2*w.y; a22 += x2*w.z; a23 += x2*w.w;
            a30 += x3*w.x; a31 += x3*w.y; a32 += x3*w.z; a33 += x3*w.w;
        }
        size_t base = (size_t)t * (64 * 64);
        float* y0 = Y + base + (size_t)tr * 64 + tc;
        *(float4*)(y0 + 0*64) = make_float4(a00, a01, a02, a03);
        *(float4*)(y0 + 1*64) = make_float4(a10, a11, a12, a13);
        *(float4*)(y0 + 2*64) = make_float4(a20, a21, a22, a23);
        *(float4*)(y0 + 3*64) = make_float4(a30, a31, a32, a33);
    }
}

// ---- decoder, CSR order, 2-edge unrolled ------------------------------------
__global__ void __launch_bounds__(256)
k_dec_csr(const float* __restrict__ A, const float* __restrict__ B,
          const float* __restrict__ b1, const float* __restrict__ w2,
          const float* __restrict__ b2, float* __restrict__ out, int N) {
    int warp = threadIdx.x >> 5, lane = threadIdx.x & 31;
    int n = blockIdx.x * 8 + warp;
    if (n >= N) return;
    int lane2 = lane * 2;
    float2 bias = *(const float2*)(b1 + lane2);
    float2 w    = *(const float2*)(w2 + lane2);
    float  bout = b2[0];
    float2 bc   = *(const float2*)(B + ((size_t)n << 6) + lane2);
    bc.x += bias.x; bc.y += bias.y;
    int st = g_offs[n];
    int en = st + g_cnti[n];
    int k = st;
    #pragma unroll 1
    for (; k + 2 <= en; k += 2) {
        uint2 rec0 = g_csr[k];
        uint2 rec1 = g_csr[k + 1];
        int r0 = (int)rec0.x, r1 = (int)rec1.x;
        float2 a0 = *(const float2*)(A + ((size_t)r0 << 6) + lane2);
        float2 a1 = *(const float2*)(A + ((size_t)r1 << 6) + lane2);
        float s0 = fmaxf(a0.x + bc.x, 0.f) * w.x + fmaxf(a0.y + bc.y, 0.f) * w.y;
        float s1 = fmaxf(a1.x + bc.x, 0.f) * w.x + fmaxf(a1.y + bc.y, 0.f) * w.y;
        #pragma unroll
        for (int off = 16; off; off >>= 1) {
            s0 += __shfl_down_sync(0xffffffffu, s0, off);
            s1 += __shfl_down_sync(0xffffffffu, s1, off);
        }
        if (lane == 0) {
            float v0 = s0 + bout;
            float v1 = s1 + bout;
            if (r0 == n) v0 = fmaxf(v0, 0.f) + log1pf(expf(-fabsf(v0)));
            if (r1 == n) v1 = fmaxf(v1, 0.f) + log1pf(expf(-fabsf(v1)));
            out[g_eid[k]]     = v0;
            out[g_eid[k + 1]] = v1;
        }
    }
    if (k < en) {
        uint2 rec = g_csr[k];
        int r = (int)rec.x;
        float2 a = *(const float2*)(A + ((size_t)r << 6) + lane2);
        float s = fmaxf(a.x + bc.x, 0.f) * w.x + fmaxf(a.y + bc.y, 0.f) * w.y;
        #pragma unroll
        for (int off = 16; off; off >>= 1)
            s += __shfl_down_sync(0xffffffffu, s, off);
        if (lane == 0) {
            float val = s + bout;
            if (r == n) val = fmaxf(val, 0.f) + log1pf(expf(-fabsf(val)));
            out[g_eid[k]] = val;
        }
    }
}

extern "C" void kernel_launch(void* const* d_in, const int* in_sizes, int n_in,
                              void* d_out, int out_size) {
    const float* x        = (const float*)d_in[0];
    const float* eattr    = (const float*)d_in[1];
    const float* w_enc    = (const float*)d_in[2];
    const float* b_enc    = (const float*)d_in[3];
    const float* conv1_w  = (const float*)d_in[4];
    const float* conv1_b  = (const float*)d_in[5];
    const float* conv2_w  = (const float*)d_in[6];
    const float* conv2_b  = (const float*)d_in[7];
    const float* dec_w1   = (const float*)d_in[8];
    const float* dec_b1   = (const float*)d_in[9];
    const float* dec_w2   = (const float*)d_in[10];
    const float* dec_b2   = (const float*)d_in[11];
    const void*  rowp     = d_in[12];
    const void*  colp     = d_in[13];
    float* out = (float*)d_out;

    const int N = in_sizes[0];
    const int E = in_sizes[1];

    float *p_deg, *p_t0, *p_t1;
    int *p_cnti;
    __half2 *p_hh0, *p_hh1;
    cudaGetSymbolAddress((void**)&p_deg, g_deg);
    cudaGetSymbolAddress((void**)&p_t0,  g_t0);
    cudaGetSymbolAddress((void**)&p_t1,  g_t1);
    cudaGetSymbolAddress((void**)&p_cnti, g_cnti);
    cudaGetSymbolAddress((void**)&p_hh0, g_hh0);
    cudaGetSymbolAddress((void**)&p_hh1, g_hh1);

    const int TB = 256;
    int eb  = (E + TB - 1) / TB;
    int nb  = (N + TB - 1) / TB;
    int nhb = (N * 32 + TB - 1) / TB;
    int ntiles = (N + 63) / 64;
    int gg  = (ntiles + 1) / 2;
    int ab  = (N + 7) / 8;
    int nsb = (N + 1023) / 1024;

    k_detect<<<1, 64>>>((const unsigned int*)rowp);

    k_zero2<<<nb, TB>>>(p_deg, p_cnti, N);
    k_deg_cnt<<<eb, TB>>>(eattr, colp, E);

    k_scan1<<<nsb, 256>>>(N);
    k_scan2<<<1, 32>>>(nsb);
    k_scan3<<<nb, TB>>>(N);
    k_csr_fill<<<eb, TB>>>(eattr, rowp, colp, E);

    // layer 1 (collapsed rank-2 form) -> hh0 (fp16)
    k_uv<<<1, 64>>>(w_enc, b_enc, conv1_w);
    k_l1sums<<<ab, TB>>>(x, N);
    k_l1out<<<nhb, TB>>>(conv1_b, p_hh0, N);

    // layers 2..6
    const float* Ws[5] = { conv2_w,            conv1_w + 4096, conv2_w + 4096,
                           conv1_w + 2*4096,   conv2_w + 2*4096 };
    const float* Bs[5] = { conv2_b,            conv1_b + 64,   conv2_b + 64,
                           conv1_b + 2*64,     conv2_b + 2*64 };
    __half2* cur = p_hh0;
    __half2* nxt = p_hh1;
    for (int i = 0; i < 5; i++) {
        k_agg<<<ab, TB>>>(cur, p_t1, N);
        k_gemm_f2h<<<gg, TB>>>(p_t1, Ws[i], Bs[i], nxt, ntiles);
        { __half2* t = cur; cur = nxt; nxt = t; }
    }

    // decoder halves
    k_gemm_h2f<<<gg, TB>>>(cur, dec_w1,        p_t0, ntiles);
    k_gemm_h2f<<<gg, TB>>>(cur, dec_w1 + 4096, p_t1, ntiles);
    k_dec_csr<<<ab, TB>>>(p_t0, p_t1, dec_b1, dec_w2, dec_b2, out, N);
}

// round 13
// speedup vs baseline: 1.8351x; 1.0899x over previous
#include <cuda_runtime.h>
#include <cuda_fp16.h>
#include <math.h>

#define L 64
static const int NMAX = 100352;
static const int EMAX = 1605632;

__device__ __align__(16) float g_deg[NMAX];
__device__ __align__(16) float g_dinv[NMAX];
__device__ __align__(16) float g_rcp[NMAX];
__device__ __align__(16) float g_a[NMAX];
__device__ __align__(16) float g_c[NMAX];
__device__ int   g_cnti[NMAX];
__device__ int   g_offs[NMAX];
__device__ int   g_cursor[NMAX];
__device__ int   g_bsums[1024];
__device__ __align__(16) uint2 g_csr[EMAX];   // .x = row idx, .y = norm bits
__device__ __align__(16) int   g_eid[EMAX];
__device__ __align__(16) float g_u[64];
__device__ __align__(16) float g_v[64];
__device__ __align__(16) __half2 g_hh0[(size_t)NMAX * 32];
__device__ __align__(16) __half2 g_hh1[(size_t)NMAX * 32];
__device__ __align__(16) float g_t0[(size_t)NMAX * L];
__device__ __align__(16) float g_t1[(size_t)NMAX * L];
__device__ int   g_is64;

__global__ void k_detect(const unsigned int* er) {
    if (blockIdx.x == 0 && threadIdx.x == 0) {
        int ok = 1;
        #pragma unroll
        for (int i = 0; i < 64; i++)
            if (er[2 * i + 1] != 0u) ok = 0;
        g_is64 = ok;
    }
}

__device__ __forceinline__ int ld_idx(const void* p, int e, int is64) {
    if (is64) return (int)((const long long*)p)[e];
    return ((const int*)p)[e];
}

__global__ void k_zero2(float* pf, int* pi, int n) {
    int i = blockIdx.x * blockDim.x + threadIdx.x;
    if (i < n) { pf[i] = 0.0f; pi[i] = 0; }
}

__global__ void k_deg_cnt(const float* __restrict__ attr, const void* colp, int E) {
    int is64 = g_is64;
    int e = blockIdx.x * blockDim.x + threadIdx.x;
    if (e < E) {
        int c = ld_idx(colp, e, is64);
        atomicAdd(&g_deg[c], attr[e]);
        atomicAdd(&g_cnti[c], 1);
    }
}

// ---------------- prefix scan over counts -----------------------------------
__global__ void k_scan1(int N) {
    __shared__ int wsum[8];
    int t = threadIdx.x;
    int base = blockIdx.x * 1024 + t * 4;
    int v0 = 0, v1 = 0, v2 = 0, v3 = 0;
    if (base + 0 < N) v0 = g_cnti[base + 0];
    if (base + 1 < N) v1 = g_cnti[base + 1];
    if (base + 2 < N) v2 = g_cnti[base + 2];
    if (base + 3 < N) v3 = g_cnti[base + 3];
    int s = v0 + v1 + v2 + v3;
    int lane = t & 31, warp = t >> 5;
    int x = s;
    #pragma unroll
    for (int o = 1; o < 32; o <<= 1) {
        int y = __shfl_up_sync(0xffffffffu, x, o);
        if (lane >= o) x += y;
    }
    if (lane == 31) wsum[warp] = x;
    __syncthreads();
    if (warp == 0 && lane < 8) {
        int w = wsum[lane];
        #pragma unroll
        for (int o = 1; o < 8; o <<= 1) {
            int y = __shfl_up_sync(0x000000ffu, w, o);
            if (lane >= o) w += y;
        }
        wsum[lane] = w;
    }
    __syncthreads();
    int excl = x - s + (warp > 0 ? wsum[warp - 1] : 0);
    int r = excl;
    r += v0; if (base + 0 < N) g_offs[base + 0] = r;
    r += v1; if (base + 1 < N) g_offs[base + 1] = r;
    r += v2; if (base + 2 < N) g_offs[base + 2] = r;
    r += v3; if (base + 3 < N) g_offs[base + 3] = r;
    if (t == 255) g_bsums[blockIdx.x] = excl + s;
}

__global__ void k_scan2(int nb) {
    if (threadIdx.x == 0 && blockIdx.x == 0) {
        int run = 0;
        for (int i = 0; i < nb; i++) { int t = g_bsums[i]; g_bsums[i] = run; run += t; }
    }
}

__global__ void k_scan3(int N) {
    int i = blockIdx.x * blockDim.x + threadIdx.x;
    if (i < N) {
        int cnt = g_cnti[i];
        int excl = g_offs[i] + g_bsums[i >> 10] - cnt;
        g_offs[i] = excl;
        g_cursor[i] = excl;
        float d = g_deg[i];
        g_dinv[i] = (d > 0.0f) ? rsqrtf(fmaxf(d, 1e-30f)) : 0.0f;
        g_rcp[i]  = 1.0f / fmaxf((float)cnt, 1.0f);
    }
}

__global__ void k_csr_fill(const float* __restrict__ attr, const void* rowp,
                           const void* colp, int E) {
    int is64 = g_is64;
    int e = blockIdx.x * blockDim.x + threadIdx.x;
    if (e < E) {
        int r = ld_idx(rowp, e, is64);
        int c = ld_idx(colp, e, is64);
        int p = atomicAdd(&g_cursor[c], 1);
        uint2 rec;
        rec.x = (unsigned int)r;
        rec.y = __float_as_uint(g_dinv[r] * attr[e] * g_dinv[c]);
        g_csr[p] = rec;
        g_eid[p] = e;
    }
}

__global__ void k_uv(const float* __restrict__ w_enc, const float* __restrict__ b_enc,
                     const float* __restrict__ W) {
    int g = threadIdx.x;
    float u = 0.f, v = 0.f;
    #pragma unroll
    for (int f = 0; f < 64; f++) {
        float wf = W[f * 64 + g];
        u += w_enc[f] * wf;
        v += b_enc[f] * wf;
    }
    g_u[g] = u;
    g_v[g] = v;
}

__global__ void __launch_bounds__(256)
k_l1sums(const float* __restrict__ x, int N) {
    int warp = threadIdx.x >> 5, lane = threadIdx.x & 31;
    int n = blockIdx.x * 8 + warp;
    if (n >= N) return;
    int st = g_offs[n];
    int en = st + g_cnti[n];
    float s1 = 0.f, s0 = 0.f;
    for (int k = st + lane; k < en; k += 32) {
        uint2 rec = g_csr[k];
        float nm = __uint_as_float(rec.y);
        s1 += nm * x[rec.x];
        s0 += nm;
    }
    #pragma unroll
    for (int off = 16; off; off >>= 1) {
        s1 += __shfl_down_sync(0xffffffffu, s1, off);
        s0 += __shfl_down_sync(0xffffffffu, s0, off);
    }
    if (lane == 0) {
        float rcp = g_rcp[n];
        g_a[n] = s1 * rcp;
        g_c[n] = s0 * rcp;
    }
}

__global__ void k_l1out(const float* __restrict__ b1, __half2* __restrict__ hout, int N) {
    int i = blockIdx.x * blockDim.x + threadIdx.x;   // over N*32 half2
    if (i < N * 32) {
        int n = i >> 5, f2 = (i & 31) * 2;
        float an = g_a[n], cn = g_c[n];
        float v0 = fmaxf(an * g_u[f2]     + cn * g_v[f2]     + b1[f2],     0.f);
        float v1 = fmaxf(an * g_u[f2 + 1] + cn * g_v[f2 + 1] + b1[f2 + 1], 0.f);
        hout[i] = __floats2half2_rn(v0, v1);
    }
}

// ---- aggregation over fp16 h (unchanged from R12) ---------------------------
__global__ void __launch_bounds__(256)
k_agg(const __half2* __restrict__ hin, float* __restrict__ aggo, int N) {
    int warp = threadIdx.x >> 5, lane = threadIdx.x & 31;
    int n = blockIdx.x * 8 + warp;
    if (n >= N) return;
    int g  = lane >> 3;
    int sl = lane & 7;
    int st = g_offs[n];
    int en = st + g_cnti[n];
    float2 a0 = make_float2(0.f, 0.f), a1 = a0, a2 = a0, a3 = a0;
    #pragma unroll 1
    for (int k = st; k < en; k += 4) {
        int e = k + g;
        int ec = e < en - 1 ? e : en - 1;
        uint2 rec = g_csr[ec];
        float nm = (e < en) ? __uint_as_float(rec.y) : 0.f;
        const uint4 v = ((const uint4*)(hin + ((size_t)rec.x << 5)))[sl];
        float2 f0 = __half22float2(*(const __half2*)&v.x);
        float2 f1 = __half22float2(*(const __half2*)&v.y);
        float2 f2 = __half22float2(*(const __half2*)&v.z);
        float2 f3 = __half22float2(*(const __half2*)&v.w);
        a0.x += f0.x * nm; a0.y += f0.y * nm;
        a1.x += f1.x * nm; a1.y += f1.y * nm;
        a2.x += f2.x * nm; a2.y += f2.y * nm;
        a3.x += f3.x * nm; a3.y += f3.y * nm;
    }
    #pragma unroll
    for (int off = 8; off <= 16; off <<= 1) {
        a0.x += __shfl_xor_sync(0xffffffffu, a0.x, off);
        a0.y += __shfl_xor_sync(0xffffffffu, a0.y, off);
        a1.x += __shfl_xor_sync(0xffffffffu, a1.x, off);
        a1.y += __shfl_xor_sync(0xffffffffu, a1.y, off);
        a2.x += __shfl_xor_sync(0xffffffffu, a2.x, off);
        a2.y += __shfl_xor_sync(0xffffffffu, a2.y, off);
        a3.x += __shfl_xor_sync(0xffffffffu, a3.x, off);
        a3.y += __shfl_xor_sync(0xffffffffu, a3.y, off);
    }
    if (lane < 8) {
        float rcp = g_rcp[n];
        float4 oA = make_float4(a0.x * rcp, a0.y * rcp, a1.x * rcp, a1.y * rcp);
        float4 oB = make_float4(a2.x * rcp, a2.y * rcp, a3.x * rcp, a3.y * rcp);
        float* y = aggo + ((size_t)n << 6) + sl * 8;
        *(float4*)(y + 0) = oA;
        *(float4*)(y + 4) = oB;
    }
}

// ---- tensor-core GEMM helpers -----------------------------------------------
__device__ __forceinline__ void mma16816(float* c, unsigned a0, unsigned a1,
                                         unsigned a2, unsigned a3,
                                         unsigned b0, unsigned b1) {
    asm volatile(
        "mma.sync.aligned.m16n8k16.row.col.f32.f16.f16.f32 "
        "{%0,%1,%2,%3}, {%4,%5,%6,%7}, {%8,%9}, {%0,%1,%2,%3};"
        : "+f"(c[0]), "+f"(c[1]), "+f"(c[2]), "+f"(c[3])
        : "r"(a0), "r"(a1), "r"(a2), "r"(a3), "r"(b0), "r"(b1));
}

// Fragment map (m16n8k16, f16): g = lane>>2, t = lane&3
//  A: a0 = X[wm+g][kk+2t..+1], a1 = X[wm+g+8][...], a2 = +8 cols, a3 = both
//  B: b0 = Wt[n][kk+2t..+1], b1 = Wt[n][kk+2t+8..+9],  n = col group id
//  C: c0,c1 = (row wm+g, cols 2t,2t+1); c2,c3 = row+8 same cols

// ---- MMA GEMM: fp32 X -> fp16 h out (+bias, relu). 64-row tiles, 8 warps. --
__global__ void __launch_bounds__(256)
k_gemm_mma_f2h(const float* __restrict__ X, const float* __restrict__ W,
               const float* __restrict__ bias, __half2* __restrict__ Y, int ntiles) {
    __shared__ __half Xs[64][72];
    __shared__ __half Wt[64][72];   // transposed W: Wt[n][k]
    int tid = threadIdx.x;
    int warp = tid >> 5, lane = tid & 31;
    int g = lane >> 2, t = lane & 3;
    int wm = (warp >> 1) * 16;
    int wn = (warp & 1) * 32;
    for (int idx = tid; idx < 4096; idx += 256) {
        int k = idx >> 6, n = idx & 63;
        Wt[n][k] = __float2half(W[idx]);
    }
    float2 bb[4];
    #pragma unroll
    for (int nt = 0; nt < 4; nt++)
        bb[nt] = *(const float2*)(bias + wn + nt * 8 + 2 * t);

    for (int tt = blockIdx.x; tt < ntiles; tt += gridDim.x) {
        __syncthreads();
        size_t base = (size_t)tt * 4096;
        const float4* X4 = (const float4*)(X + base);
        #pragma unroll
        for (int i = 0; i < 4; i++) {
            int idx = tid + i * 256;
            float4 v = X4[idx];
            int row = idx >> 4, c0 = (idx & 15) * 4;
            __half2 h0 = __floats2half2_rn(v.x, v.y);
            __half2 h1 = __floats2half2_rn(v.z, v.w);
            *(uint2*)&Xs[row][c0] = make_uint2(*(unsigned*)&h0, *(unsigned*)&h1);
        }
        __syncthreads();
        float c[4][4];
        #pragma unroll
        for (int nt = 0; nt < 4; nt++)
            c[nt][0] = c[nt][1] = c[nt][2] = c[nt][3] = 0.f;
        #pragma unroll
        for (int kk = 0; kk < 64; kk += 16) {
            unsigned a0 = *(const unsigned*)&Xs[wm + g][kk + 2 * t];
            unsigned a1 = *(const unsigned*)&Xs[wm + g + 8][kk + 2 * t];
            unsigned a2 = *(const unsigned*)&Xs[wm + g][kk + 2 * t + 8];
            unsigned a3 = *(const unsigned*)&Xs[wm + g + 8][kk + 2 * t + 8];
            #pragma unroll
            for (int nt = 0; nt < 4; nt++) {
                int n = wn + nt * 8 + g;
                unsigned b0 = *(const unsigned*)&Wt[n][kk + 2 * t];
                unsigned b1 = *(const unsigned*)&Wt[n][kk + 2 * t + 8];
                mma16816(c[nt], a0, a1, a2, a3, b0, b1);
            }
        }
        size_t ybase = (size_t)tt * 2048;   // half2 per tile: 64*32
        int colh = (wn >> 1) + t;           // half2 column base (per nt add 4)
        #pragma unroll
        for (int nt = 0; nt < 4; nt++) {
            float o0 = fmaxf(c[nt][0] + bb[nt].x, 0.f);
            float o1 = fmaxf(c[nt][1] + bb[nt].y, 0.f);
            float o2 = fmaxf(c[nt][2] + bb[nt].x, 0.f);
            float o3 = fmaxf(c[nt][3] + bb[nt].y, 0.f);
            Y[ybase + (size_t)(wm + g) * 32 + colh + nt * 4]     = __floats2half2_rn(o0, o1);
            Y[ybase + (size_t)(wm + g + 8) * 32 + colh + nt * 4] = __floats2half2_rn(o2, o3);
        }
    }
}

// ---- MMA GEMM: fp16 X -> fp32 out (decoder halves, no bias/relu) ------------
__global__ void __launch_bounds__(256)
k_gemm_mma_h2f(const __half2* __restrict__ X, const float* __restrict__ W,
               float* __restrict__ Y, int ntiles) {
    __shared__ __half Xs[64][72];
    __shared__ __half Wt[64][72];
    int tid = threadIdx.x;
    int warp = tid >> 5, lane = tid & 31;
    int g = lane >> 2, t = lane & 3;
    int wm = (warp >> 1) * 16;
    int wn = (warp & 1) * 32;
    for (int idx = tid; idx < 4096; idx += 256) {
        int k = idx >> 6, n = idx & 63;
        Wt[n][k] = __float2half(W[idx]);
    }

    for (int tt = blockIdx.x; tt < ntiles; tt += gridDim.x) {
        __syncthreads();
        size_t hbase = (size_t)tt * 2048;         // half2 units
        const uint4* X4 = (const uint4*)(X + hbase);
        #pragma unroll
        for (int i = 0; i < 2; i++) {
            int idx = tid + i * 256;              // 0..511 uint4 (8 halves each)
            uint4 v = X4[idx];
            int row = idx >> 3;
            int c0  = (idx & 7) * 8;
            *(uint4*)&Xs[row][c0] = v;            // 144B row stride: 16B aligned
        }
        __syncthreads();
        float c[4][4];
        #pragma unroll
        for (int nt = 0; nt < 4; nt++)
            c[nt][0] = c[nt][1] = c[nt][2] = c[nt][3] = 0.f;
        #pragma unroll
        for (int kk = 0; kk < 64; kk += 16) {
            unsigned a0 = *(const unsigned*)&Xs[wm + g][kk + 2 * t];
            unsigned a1 = *(const unsigned*)&Xs[wm + g + 8][kk + 2 * t];
            unsigned a2 = *(const unsigned*)&Xs[wm + g][kk + 2 * t + 8];
            unsigned a3 = *(const unsigned*)&Xs[wm + g + 8][kk + 2 * t + 8];
            #pragma unroll
            for (int nt = 0; nt < 4; nt++) {
                int n = wn + nt * 8 + g;
                unsigned b0 = *(const unsigned*)&Wt[n][kk + 2 * t];
                unsigned b1 = *(const unsigned*)&Wt[n][kk + 2 * t + 8];
                mma16816(c[nt], a0, a1, a2, a3, b0, b1);
            }
        }
        size_t base = (size_t)tt * 4096;
        #pragma unroll
        for (int nt = 0; nt < 4; nt++) {
            int col = wn + nt * 8 + 2 * t;
            *(float2*)(Y + base + (size_t)(wm + g) * 64 + col)     = make_float2(c[nt][0], c[nt][1]);
            *(float2*)(Y + base + (size_t)(wm + g + 8) * 64 + col) = make_float2(c[nt][2], c[nt][3]);
        }
    }
}

// ---- decoder, CSR order, 2-edge unrolled (unchanged) ------------------------
__global__ void __launch_bounds__(256)
k_dec_csr(const float* __restrict__ A, const float* __restrict__ B,
          const float* __restrict__ b1, const float* __restrict__ w2,
          const float* __restrict__ b2, float* __restrict__ out, int N) {
    int warp = threadIdx.x >> 5, lane = threadIdx.x & 31;
    int n = blockIdx.x * 8 + warp;
    if (n >= N) return;
    int lane2 = lane * 2;
    float2 bias = *(const float2*)(b1 + lane2);
    float2 w    = *(const float2*)(w2 + lane2);
    float  bout = b2[0];
    float2 bc   = *(const float2*)(B + ((size_t)n << 6) + lane2);
    bc.x += bias.x; bc.y += bias.y;
    int st = g_offs[n];
    int en = st + g_cnti[n];
    int k = st;
    #pragma unroll 1
    for (; k + 2 <= en; k += 2) {
        uint2 rec0 = g_csr[k];
        uint2 rec1 = g_csr[k + 1];
        int r0 = (int)rec0.x, r1 = (int)rec1.x;
        float2 a0 = *(const float2*)(A + ((size_t)r0 << 6) + lane2);
        float2 a1 = *(const float2*)(A + ((size_t)r1 << 6) + lane2);
        float s0 = fmaxf(a0.x + bc.x, 0.f) * w.x + fmaxf(a0.y + bc.y, 0.f) * w.y;
        float s1 = fmaxf(a1.x + bc.x, 0.f) * w.x + fmaxf(a1.y + bc.y, 0.f) * w.y;
        #pragma unroll
        for (int off = 16; off; off >>= 1) {
            s0 += __shfl_down_sync(0xffffffffu, s0, off);
            s1 += __shfl_down_sync(0xffffffffu, s1, off);
        }
        if (lane == 0) {
            float v0 = s0 + bout;
            float v1 = s1 + bout;
            if (r0 == n) v0 = fmaxf(v0, 0.f) + log1pf(expf(-fabsf(v0)));
            if (r1 == n) v1 = fmaxf(v1, 0.f) + log1pf(expf(-fabsf(v1)));
            out[g_eid[k]]     = v0;
            out[g_eid[k + 1]] = v1;
        }
    }
    if (k < en) {
        uint2 rec = g_csr[k];
        int r = (int)rec.x;
        float2 a = *(const float2*)(A + ((size_t)r << 6) + lane2);
        float s = fmaxf(a.x + bc.x, 0.f) * w.x + fmaxf(a.y + bc.y, 0.f) * w.y;
        #pragma unroll
        for (int off = 16; off; off >>= 1)
            s += __shfl_down_sync(0xffffffffu, s, off);
        if (lane == 0) {
            float val = s + bout;
            if (r == n) val = fmaxf(val, 0.f) + log1pf(expf(-fabsf(val)));
            out[g_eid[k]] = val;
        }
    }
}

extern "C" void kernel_launch(void* const* d_in, const int* in_sizes, int n_in,
                              void* d_out, int out_size) {
    const float* x        = (const float*)d_in[0];
    const float* eattr    = (const float*)d_in[1];
    const float* w_enc    = (const float*)d_in[2];
    const float* b_enc    = (const float*)d_in[3];
    const float* conv1_w  = (const float*)d_in[4];
    const float* conv1_b  = (const float*)d_in[5];
    const float* conv2_w  = (const float*)d_in[6];
    const float* conv2_b  = (const float*)d_in[7];
    const float* dec_w1   = (const float*)d_in[8];
    const float* dec_b1   = (const float*)d_in[9];
    const float* dec_w2   = (const float*)d_in[10];
    const float* dec_b2   = (const float*)d_in[11];
    const void*  rowp     = d_in[12];
    const void*  colp     = d_in[13];
    float* out = (float*)d_out;

    const int N = in_sizes[0];
    const int E = in_sizes[1];

    float *p_deg, *p_t0, *p_t1;
    int *p_cnti;
    __half2 *p_hh0, *p_hh1;
    cudaGetSymbolAddress((void**)&p_deg, g_deg);
    cudaGetSymbolAddress((void**)&p_t0,  g_t0);
    cudaGetSymbolAddress((void**)&p_t1,  g_t1);
    cudaGetSymbolAddress((void**)&p_cnti, g_cnti);
    cudaGetSymbolAddress((void**)&p_hh0, g_hh0);
    cudaGetSymbolAddress((void**)&p_hh1, g_hh1);

    const int TB = 256;
    int eb  = (E + TB - 1) / TB;
    int nb  = (N + TB - 1) / TB;
    int nhb = (N * 32 + TB - 1) / TB;
    int ntiles = (N + 63) / 64;
    int gg  = (ntiles + 1) / 2;
    int ab  = (N + 7) / 8;
    int nsb = (N + 1023) / 1024;

    k_detect<<<1, 64>>>((const unsigned int*)rowp);

    k_zero2<<<nb, TB>>>(p_deg, p_cnti, N);
    k_deg_cnt<<<eb, TB>>>(eattr, colp, E);

    k_scan1<<<nsb, 256>>>(N);
    k_scan2<<<1, 32>>>(nsb);
    k_scan3<<<nb, TB>>>(N);
    k_csr_fill<<<eb, TB>>>(eattr, rowp, colp, E);

    // layer 1 (collapsed rank-2 form) -> hh0 (fp16)
    k_uv<<<1, 64>>>(w_enc, b_enc, conv1_w);
    k_l1sums<<<ab, TB>>>(x, N);
    k_l1out<<<nhb, TB>>>(conv1_b, p_hh0, N);

    // layers 2..6: agg(fp16 -> f32 t1), MMA gemm(f32 t1 -> fp16 h)
    const float* Ws[5] = { conv2_w,            conv1_w + 4096, conv2_w + 4096,
                           conv1_w + 2*4096,   conv2_w + 2*4096 };
    const float* Bs[5] = { conv2_b,            conv1_b + 64,   conv2_b + 64,
                           conv1_b + 2*64,     conv2_b + 2*64 };
    __half2* cur = p_hh0;
    __half2* nxt = p_hh1;
    for (int i = 0; i < 5; i++) {
        k_agg<<<ab, TB>>>(cur, p_t1, N);
        k_gemm_mma_f2h<<<gg, TB>>>(p_t1, Ws[i], Bs[i], nxt, ntiles);
        { __half2* t = cur; cur = nxt; nxt = t; }
    }

    // decoder halves: A = h6 @ W1_top -> t0 ; B = h6 @ W1_bot -> t1
    k_gemm_mma_h2f<<<gg, TB>>>(cur, dec_w1,        p_t0, ntiles);
    k_gemm_mma_h2f<<<gg, TB>>>(cur, dec_w1 + 4096, p_t1, ntiles);
    k_dec_csr<<<ab, TB>>>(p_t0, p_t1, dec_b1, dec_w2, dec_b2, out, N);
}

// round 14
// speedup vs baseline: 1.8769x; 1.0228x over previous
#include <cuda_runtime.h>
#include <cuda_fp16.h>
#include <math.h>

#define L 64
static const int NMAX = 100352;
static const int EMAX = 1605632;

__device__ __align__(16) float g_deg[NMAX];
__device__ __align__(16) float g_dinv[NMAX];
__device__ __align__(16) float g_rcp[NMAX];
__device__ __align__(16) float g_a[NMAX];
__device__ __align__(16) float g_c[NMAX];
__device__ int   g_cnti[NMAX];
__device__ int   g_offs[NMAX];
__device__ int   g_cursor[NMAX];
__device__ int   g_bsums[1024];
__device__ __align__(16) uint2 g_csr[EMAX];   // .x = row idx, .y = norm bits
__device__ __align__(16) int   g_eid[EMAX];
__device__ __align__(16) float g_u[64];
__device__ __align__(16) float g_v[64];
__device__ __align__(16) __half2 g_hh0[(size_t)NMAX * 32];
__device__ __align__(16) __half2 g_hh1[(size_t)NMAX * 32];
__device__ __align__(16) float g_t0[(size_t)NMAX * L];
__device__ __align__(16) float g_t1[(size_t)NMAX * L];
__device__ int   g_is64;

__global__ void k_detect(const unsigned int* er) {
    if (blockIdx.x == 0 && threadIdx.x == 0) {
        int ok = 1;
        #pragma unroll
        for (int i = 0; i < 64; i++)
            if (er[2 * i + 1] != 0u) ok = 0;
        g_is64 = ok;
    }
}

__device__ __forceinline__ int ld_idx(const void* p, int e, int is64) {
    if (is64) return (int)((const long long*)p)[e];
    return ((const int*)p)[e];
}

__global__ void k_zero2(float* pf, int* pi, int n) {
    int i = blockIdx.x * blockDim.x + threadIdx.x;
    if (i < n) { pf[i] = 0.0f; pi[i] = 0; }
}

__global__ void k_deg_cnt(const float* __restrict__ attr, const void* colp, int E) {
    int is64 = g_is64;
    int e = blockIdx.x * blockDim.x + threadIdx.x;
    if (e < E) {
        int c = ld_idx(colp, e, is64);
        atomicAdd(&g_deg[c], attr[e]);
        atomicAdd(&g_cnti[c], 1);
    }
}

// ---------------- prefix scan over counts -----------------------------------
__global__ void k_scan1(int N) {
    __shared__ int wsum[8];
    int t = threadIdx.x;
    int base = blockIdx.x * 1024 + t * 4;
    int v0 = 0, v1 = 0, v2 = 0, v3 = 0;
    if (base + 0 < N) v0 = g_cnti[base + 0];
    if (base + 1 < N) v1 = g_cnti[base + 1];
    if (base + 2 < N) v2 = g_cnti[base + 2];
    if (base + 3 < N) v3 = g_cnti[base + 3];
    int s = v0 + v1 + v2 + v3;
    int lane = t & 31, warp = t >> 5;
    int x = s;
    #pragma unroll
    for (int o = 1; o < 32; o <<= 1) {
        int y = __shfl_up_sync(0xffffffffu, x, o);
        if (lane >= o) x += y;
    }
    if (lane == 31) wsum[warp] = x;
    __syncthreads();
    if (warp == 0 && lane < 8) {
        int w = wsum[lane];
        #pragma unroll
        for (int o = 1; o < 8; o <<= 1) {
            int y = __shfl_up_sync(0x000000ffu, w, o);
            if (lane >= o) w += y;
        }
        wsum[lane] = w;
    }
    __syncthreads();
    int excl = x - s + (warp > 0 ? wsum[warp - 1] : 0);
    int r = excl;
    r += v0; if (base + 0 < N) g_offs[base + 0] = r;
    r += v1; if (base + 1 < N) g_offs[base + 1] = r;
    r += v2; if (base + 2 < N) g_offs[base + 2] = r;
    r += v3; if (base + 3 < N) g_offs[base + 3] = r;
    if (t == 255) g_bsums[blockIdx.x] = excl + s;
}

__global__ void k_scan2(int nb) {
    if (threadIdx.x == 0 && blockIdx.x == 0) {
        int run = 0;
        for (int i = 0; i < nb; i++) { int t = g_bsums[i]; g_bsums[i] = run; run += t; }
    }
}

__global__ void k_scan3(int N) {
    int i = blockIdx.x * blockDim.x + threadIdx.x;
    if (i < N) {
        int cnt = g_cnti[i];
        int excl = g_offs[i] + g_bsums[i >> 10] - cnt;
        g_offs[i] = excl;
        g_cursor[i] = excl;
        float d = g_deg[i];
        g_dinv[i] = (d > 0.0f) ? rsqrtf(fmaxf(d, 1e-30f)) : 0.0f;
        g_rcp[i]  = 1.0f / fmaxf((float)cnt, 1.0f);
    }
}

__global__ void k_csr_fill(const float* __restrict__ attr, const void* rowp,
                           const void* colp, int E) {
    int is64 = g_is64;
    int e = blockIdx.x * blockDim.x + threadIdx.x;
    if (e < E) {
        int r = ld_idx(rowp, e, is64);
        int c = ld_idx(colp, e, is64);
        int p = atomicAdd(&g_cursor[c], 1);
        uint2 rec;
        rec.x = (unsigned int)r;
        rec.y = __float_as_uint(g_dinv[r] * attr[e] * g_dinv[c]);
        g_csr[p] = rec;
        g_eid[p] = e;
    }
}

__global__ void k_uv(const float* __restrict__ w_enc, const float* __restrict__ b_enc,
                     const float* __restrict__ W) {
    int g = threadIdx.x;
    float u = 0.f, v = 0.f;
    #pragma unroll
    for (int f = 0; f < 64; f++) {
        float wf = W[f * 64 + g];
        u += w_enc[f] * wf;
        v += b_enc[f] * wf;
    }
    g_u[g] = u;
    g_v[g] = v;
}

__global__ void __launch_bounds__(256)
k_l1sums(const float* __restrict__ x, int N) {
    int warp = threadIdx.x >> 5, lane = threadIdx.x & 31;
    int n = blockIdx.x * 8 + warp;
    if (n >= N) return;
    int st = g_offs[n];
    int en = st + g_cnti[n];
    float s1 = 0.f, s0 = 0.f;
    for (int k = st + lane; k < en; k += 32) {
        uint2 rec = g_csr[k];
        float nm = __uint_as_float(rec.y);
        s1 += nm * x[rec.x];
        s0 += nm;
    }
    #pragma unroll
    for (int off = 16; off; off >>= 1) {
        s1 += __shfl_down_sync(0xffffffffu, s1, off);
        s0 += __shfl_down_sync(0xffffffffu, s0, off);
    }
    if (lane == 0) {
        float rcp = g_rcp[n];
        g_a[n] = s1 * rcp;
        g_c[n] = s0 * rcp;
    }
}

__global__ void k_l1out(const float* __restrict__ b1, __half2* __restrict__ hout, int N) {
    int i = blockIdx.x * blockDim.x + threadIdx.x;   // over N*32 half2
    if (i < N * 32) {
        int n = i >> 5, f2 = (i & 31) * 2;
        float an = g_a[n], cn = g_c[n];
        float v0 = fmaxf(an * g_u[f2]     + cn * g_v[f2]     + b1[f2],     0.f);
        float v1 = fmaxf(an * g_u[f2 + 1] + cn * g_v[f2 + 1] + b1[f2 + 1], 0.f);
        hout[i] = __floats2half2_rn(v0, v1);
    }
}

// ---- aggregation over fp16 h (unchanged from R12/R13) -----------------------
__global__ void __launch_bounds__(256)
k_agg(const __half2* __restrict__ hin, float* __restrict__ aggo, int N) {
    int warp = threadIdx.x >> 5, lane = threadIdx.x & 31;
    int n = blockIdx.x * 8 + warp;
    if (n >= N) return;
    int g  = lane >> 3;
    int sl = lane & 7;
    int st = g_offs[n];
    int en = st + g_cnti[n];
    float2 a0 = make_float2(0.f, 0.f), a1 = a0, a2 = a0, a3 = a0;
    #pragma unroll 1
    for (int k = st; k < en; k += 4) {
        int e = k + g;
        int ec = e < en - 1 ? e : en - 1;
        uint2 rec = g_csr[ec];
        float nm = (e < en) ? __uint_as_float(rec.y) : 0.f;
        const uint4 v = ((const uint4*)(hin + ((size_t)rec.x << 5)))[sl];
        float2 f0 = __half22float2(*(const __half2*)&v.x);
        float2 f1 = __half22float2(*(const __half2*)&v.y);
        float2 f2 = __half22float2(*(const __half2*)&v.z);
        float2 f3 = __half22float2(*(const __half2*)&v.w);
        a0.x += f0.x * nm; a0.y += f0.y * nm;
        a1.x += f1.x * nm; a1.y += f1.y * nm;
        a2.x += f2.x * nm; a2.y += f2.y * nm;
        a3.x += f3.x * nm; a3.y += f3.y * nm;
    }
    #pragma unroll
    for (int off = 8; off <= 16; off <<= 1) {
        a0.x += __shfl_xor_sync(0xffffffffu, a0.x, off);
        a0.y += __shfl_xor_sync(0xffffffffu, a0.y, off);
        a1.x += __shfl_xor_sync(0xffffffffu, a1.x, off);
        a1.y += __shfl_xor_sync(0xffffffffu, a1.y, off);
        a2.x += __shfl_xor_sync(0xffffffffu, a2.x, off);
        a2.y += __shfl_xor_sync(0xffffffffu, a2.y, off);
        a3.x += __shfl_xor_sync(0xffffffffu, a3.x, off);
        a3.y += __shfl_xor_sync(0xffffffffu, a3.y, off);
    }
    if (lane < 8) {
        float rcp = g_rcp[n];
        float4 oA = make_float4(a0.x * rcp, a0.y * rcp, a1.x * rcp, a1.y * rcp);
        float4 oB = make_float4(a2.x * rcp, a2.y * rcp, a3.x * rcp, a3.y * rcp);
        float* y = aggo + ((size_t)n << 6) + sl * 8;
        *(float4*)(y + 0) = oA;
        *(float4*)(y + 4) = oB;
    }
}

// ---- tensor-core GEMM helpers -----------------------------------------------
__device__ __forceinline__ void mma16816(float* c, unsigned a0, unsigned a1,
                                         unsigned a2, unsigned a3,
                                         unsigned b0, unsigned b1) {
    asm volatile(
        "mma.sync.aligned.m16n8k16.row.col.f32.f16.f16.f32 "
        "{%0,%1,%2,%3}, {%4,%5,%6,%7}, {%8,%9}, {%0,%1,%2,%3};"
        : "+f"(c[0]), "+f"(c[1]), "+f"(c[2]), "+f"(c[3])
        : "r"(a0), "r"(a1), "r"(a2), "r"(a3), "r"(b0), "r"(b1));
}

// ---- MMA GEMM: fp32 X -> fp16 h out (+bias, relu). (unchanged from R13) ----
__global__ void __launch_bounds__(256)
k_gemm_mma_f2h(const float* __restrict__ X, const float* __restrict__ W,
               const float* __restrict__ bias, __half2* __restrict__ Y, int ntiles) {
    __shared__ __half Xs[64][72];
    __shared__ __half Wt[64][72];   // transposed W: Wt[n][k]
    int tid = threadIdx.x;
    int warp = tid >> 5, lane = tid & 31;
    int g = lane >> 2, t = lane & 3;
    int wm = (warp >> 1) * 16;
    int wn = (warp & 1) * 32;
    for (int idx = tid; idx < 4096; idx += 256) {
        int k = idx >> 6, n = idx & 63;
        Wt[n][k] = __float2half(W[idx]);
    }
    float2 bb[4];
    #pragma unroll
    for (int nt = 0; nt < 4; nt++)
        bb[nt] = *(const float2*)(bias + wn + nt * 8 + 2 * t);

    for (int tt = blockIdx.x; tt < ntiles; tt += gridDim.x) {
        __syncthreads();
        size_t base = (size_t)tt * 4096;
        const float4* X4 = (const float4*)(X + base);
        #pragma unroll
        for (int i = 0; i < 4; i++) {
            int idx = tid + i * 256;
            float4 v = X4[idx];
            int row = idx >> 4, c0 = (idx & 15) * 4;
            __half2 h0 = __floats2half2_rn(v.x, v.y);
            __half2 h1 = __floats2half2_rn(v.z, v.w);
            *(uint2*)&Xs[row][c0] = make_uint2(*(unsigned*)&h0, *(unsigned*)&h1);
        }
        __syncthreads();
        float c[4][4];
        #pragma unroll
        for (int nt = 0; nt < 4; nt++)
            c[nt][0] = c[nt][1] = c[nt][2] = c[nt][3] = 0.f;
        #pragma unroll
        for (int kk = 0; kk < 64; kk += 16) {
            unsigned a0 = *(const unsigned*)&Xs[wm + g][kk + 2 * t];
            unsigned a1 = *(const unsigned*)&Xs[wm + g + 8][kk + 2 * t];
            unsigned a2 = *(const unsigned*)&Xs[wm + g][kk + 2 * t + 8];
            unsigned a3 = *(const unsigned*)&Xs[wm + g + 8][kk + 2 * t + 8];
            #pragma unroll
            for (int nt = 0; nt < 4; nt++) {
                int n = wn + nt * 8 + g;
                unsigned b0 = *(const unsigned*)&Wt[n][kk + 2 * t];
                unsigned b1 = *(const unsigned*)&Wt[n][kk + 2 * t + 8];
                mma16816(c[nt], a0, a1, a2, a3, b0, b1);
            }
        }
        size_t ybase = (size_t)tt * 2048;
        int colh = (wn >> 1) + t;
        #pragma unroll
        for (int nt = 0; nt < 4; nt++) {
            float o0 = fmaxf(c[nt][0] + bb[nt].x, 0.f);
            float o1 = fmaxf(c[nt][1] + bb[nt].y, 0.f);
            float o2 = fmaxf(c[nt][2] + bb[nt].x, 0.f);
            float o3 = fmaxf(c[nt][3] + bb[nt].y, 0.f);
            Y[ybase + (size_t)(wm + g) * 32 + colh + nt * 4]     = __floats2half2_rn(o0, o1);
            Y[ybase + (size_t)(wm + g + 8) * 32 + colh + nt * 4] = __floats2half2_rn(o2, o3);
        }
    }
}

// ---- fused decoder GEMM: fp16 X -> A (fp16, W rows 0..63), B (fp32, 64..127) -
__global__ void __launch_bounds__(256)
k_gemm_mma_dec(const __half2* __restrict__ X, const float* __restrict__ W,
               __half2* __restrict__ YA, float* __restrict__ YB, int ntiles) {
    __shared__ __half Xs[64][72];
    __shared__ __half WtA[64][72];   // WtA[n][k] = W[k][n],      k in 0..63
    __shared__ __half WtB[64][72];   // WtB[n][k] = W[k+64][n]
    int tid = threadIdx.x;
    int warp = tid >> 5, lane = tid & 31;
    int g = lane >> 2, t = lane & 3;
    int wm = (warp >> 1) * 16;
    int wn = (warp & 1) * 32;
    for (int idx = tid; idx < 4096; idx += 256) {
        int k = idx >> 6, n = idx & 63;
        WtA[n][k] = __float2half(W[idx]);
        WtB[n][k] = __float2half(W[idx + 4096]);
    }

    for (int tt = blockIdx.x; tt < ntiles; tt += gridDim.x) {
        __syncthreads();
        size_t hbase = (size_t)tt * 2048;
        const uint4* X4 = (const uint4*)(X + hbase);
        #pragma unroll
        for (int i = 0; i < 2; i++) {
            int idx = tid + i * 256;
            uint4 v = X4[idx];
            int row = idx >> 3;
            int c0  = (idx & 7) * 8;
            *(uint4*)&Xs[row][c0] = v;
        }
        __syncthreads();
        float cA[4][4], cB[4][4];
        #pragma unroll
        for (int nt = 0; nt < 4; nt++) {
            cA[nt][0] = cA[nt][1] = cA[nt][2] = cA[nt][3] = 0.f;
            cB[nt][0] = cB[nt][1] = cB[nt][2] = cB[nt][3] = 0.f;
        }
        #pragma unroll
        for (int kk = 0; kk < 64; kk += 16) {
            unsigned a0 = *(const unsigned*)&Xs[wm + g][kk + 2 * t];
            unsigned a1 = *(const unsigned*)&Xs[wm + g + 8][kk + 2 * t];
            unsigned a2 = *(const unsigned*)&Xs[wm + g][kk + 2 * t + 8];
            unsigned a3 = *(const unsigned*)&Xs[wm + g + 8][kk + 2 * t + 8];
            #pragma unroll
            for (int nt = 0; nt < 4; nt++) {
                int n = wn + nt * 8 + g;
                unsigned b0 = *(const unsigned*)&WtA[n][kk + 2 * t];
                unsigned b1 = *(const unsigned*)&WtA[n][kk + 2 * t + 8];
                mma16816(cA[nt], a0, a1, a2, a3, b0, b1);
                unsigned d0 = *(const unsigned*)&WtB[n][kk + 2 * t];
                unsigned d1 = *(const unsigned*)&WtB[n][kk + 2 * t + 8];
                mma16816(cB[nt], a0, a1, a2, a3, d0, d1);
            }
        }
        // A out: fp16
        size_t yab = (size_t)tt * 2048;
        int colh = (wn >> 1) + t;
        #pragma unroll
        for (int nt = 0; nt < 4; nt++) {
            YA[yab + (size_t)(wm + g) * 32 + colh + nt * 4]     = __floats2half2_rn(cA[nt][0], cA[nt][1]);
            YA[yab + (size_t)(wm + g + 8) * 32 + colh + nt * 4] = __floats2half2_rn(cA[nt][2], cA[nt][3]);
        }
        // B out: fp32
        size_t base = (size_t)tt * 4096;
        #pragma unroll
        for (int nt = 0; nt < 4; nt++) {
            int col = wn + nt * 8 + 2 * t;
            *(float2*)(YB + base + (size_t)(wm + g) * 64 + col)     = make_float2(cB[nt][0], cB[nt][1]);
            *(float2*)(YB + base + (size_t)(wm + g + 8) * 64 + col) = make_float2(cB[nt][2], cB[nt][3]);
        }
    }
}

// ---- decoder, CSR order, fp16 A gather --------------------------------------
__global__ void __launch_bounds__(256)
k_dec_csr(const __half2* __restrict__ A, const float* __restrict__ B,
          const float* __restrict__ b1, const float* __restrict__ w2,
          const float* __restrict__ b2, float* __restrict__ out, int N) {
    int warp = threadIdx.x >> 5, lane = threadIdx.x & 31;
    int n = blockIdx.x * 8 + warp;
    if (n >= N) return;
    int lane2 = lane * 2;
    float2 bias = *(const float2*)(b1 + lane2);
    float2 w    = *(const float2*)(w2 + lane2);
    float  bout = b2[0];
    float2 bc   = *(const float2*)(B + ((size_t)n << 6) + lane2);
    bc.x += bias.x; bc.y += bias.y;
    int st = g_offs[n];
    int en = st + g_cnti[n];
    int k = st;
    #pragma unroll 1
    for (; k + 2 <= en; k += 2) {
        uint2 rec0 = g_csr[k];
        uint2 rec1 = g_csr[k + 1];
        int r0 = (int)rec0.x, r1 = (int)rec1.x;
        float2 a0 = __half22float2(A[((size_t)r0 << 5) + lane]);
        float2 a1 = __half22float2(A[((size_t)r1 << 5) + lane]);
        float s0 = fmaxf(a0.x + bc.x, 0.f) * w.x + fmaxf(a0.y + bc.y, 0.f) * w.y;
        float s1 = fmaxf(a1.x + bc.x, 0.f) * w.x + fmaxf(a1.y + bc.y, 0.f) * w.y;
        #pragma unroll
        for (int off = 16; off; off >>= 1) {
            s0 += __shfl_down_sync(0xffffffffu, s0, off);
            s1 += __shfl_down_sync(0xffffffffu, s1, off);
        }
        if (lane == 0) {
            float v0 = s0 + bout;
            float v1 = s1 + bout;
            if (r0 == n) v0 = fmaxf(v0, 0.f) + log1pf(expf(-fabsf(v0)));
            if (r1 == n) v1 = fmaxf(v1, 0.f) + log1pf(expf(-fabsf(v1)));
            out[g_eid[k]]     = v0;
            out[g_eid[k + 1]] = v1;
        }
    }
    if (k < en) {
        uint2 rec = g_csr[k];
        int r = (int)rec.x;
        float2 a = __half22float2(A[((size_t)r << 5) + lane]);
        float s = fmaxf(a.x + bc.x, 0.f) * w.x + fmaxf(a.y + bc.y, 0.f) * w.y;
        #pragma unroll
        for (int off = 16; off; off >>= 1)
            s += __shfl_down_sync(0xffffffffu, s, off);
        if (lane == 0) {
            float val = s + bout;
            if (r == n) val = fmaxf(val, 0.f) + log1pf(expf(-fabsf(val)));
            out[g_eid[k]] = val;
        }
    }
}

extern "C" void kernel_launch(void* const* d_in, const int* in_sizes, int n_in,
                              void* d_out, int out_size) {
    const float* x        = (const float*)d_in[0];
    const float* eattr    = (const float*)d_in[1];
    const float* w_enc    = (const float*)d_in[2];
    const float* b_enc    = (const float*)d_in[3];
    const float* conv1_w  = (const float*)d_in[4];
    const float* conv1_b  = (const float*)d_in[5];
    const float* conv2_w  = (const float*)d_in[6];
    const float* conv2_b  = (const float*)d_in[7];
    const float* dec_w1   = (const float*)d_in[8];
    const float* dec_b1   = (const float*)d_in[9];
    const float* dec_w2   = (const float*)d_in[10];
    const float* dec_b2   = (const float*)d_in[11];
    const void*  rowp     = d_in[12];
    const void*  colp     = d_in[13];
    float* out = (float*)d_out;

    const int N = in_sizes[0];
    const int E = in_sizes[1];

    float *p_deg, *p_t1;
    int *p_cnti;
    __half2 *p_hh0, *p_hh1;
    cudaGetSymbolAddress((void**)&p_deg, g_deg);
    cudaGetSymbolAddress((void**)&p_t1,  g_t1);
    cudaGetSymbolAddress((void**)&p_cnti, g_cnti);
    cudaGetSymbolAddress((void**)&p_hh0, g_hh0);
    cudaGetSymbolAddress((void**)&p_hh1, g_hh1);

    const int TB = 256;
    int eb  = (E + TB - 1) / TB;
    int nb  = (N + TB - 1) / TB;
    int nhb = (N * 32 + TB - 1) / TB;
    int ntiles = (N + 63) / 64;
    int gg  = (ntiles + 1) / 2;
    int ab  = (N + 7) / 8;
    int nsb = (N + 1023) / 1024;

    k_detect<<<1, 64>>>((const unsigned int*)rowp);

    k_zero2<<<nb, TB>>>(p_deg, p_cnti, N);
    k_deg_cnt<<<eb, TB>>>(eattr, colp, E);

    k_scan1<<<nsb, 256>>>(N);
    k_scan2<<<1, 32>>>(nsb);
    k_scan3<<<nb, TB>>>(N);
    k_csr_fill<<<eb, TB>>>(eattr, rowp, colp, E);

    // layer 1 (collapsed rank-2 form) -> hh0 (fp16)
    k_uv<<<1, 64>>>(w_enc, b_enc, conv1_w);
    k_l1sums<<<ab, TB>>>(x, N);
    k_l1out<<<nhb, TB>>>(conv1_b, p_hh0, N);

    // layers 2..6: agg(fp16 -> f32 t1), MMA gemm(f32 t1 -> fp16 h)
    const float* Ws[5] = { conv2_w,            conv1_w + 4096, conv2_w + 4096,
                           conv1_w + 2*4096,   conv2_w + 2*4096 };
    const float* Bs[5] = { conv2_b,            conv1_b + 64,   conv2_b + 64,
                           conv1_b + 2*64,     conv2_b + 2*64 };
    __half2* cur = p_hh0;
    __half2* nxt = p_hh1;
    for (int i = 0; i < 5; i++) {
        k_agg<<<ab, TB>>>(cur, p_t1, N);
        k_gemm_mma_f2h<<<gg, TB>>>(p_t1, Ws[i], Bs[i], nxt, ntiles);
        { __half2* t = cur; cur = nxt; nxt = t; }
    }
    // after 5 layers: cur = hh1, nxt = hh0 (free)

    // fused decoder GEMM: A (fp16) -> nxt, B (fp32) -> t1
    k_gemm_mma_dec<<<gg, TB>>>(cur, dec_w1, nxt, p_t1, ntiles);
    k_dec_csr<<<ab, TB>>>(nxt, p_t1, dec_b1, dec_w2, dec_b2, out, N);
}

// round 15
// speedup vs baseline: 1.9524x; 1.0402x over previous
#include <cuda_runtime.h>
#include <cuda_fp16.h>
#include <math.h>

#define L 64
static const int NMAX = 100352;
static const int EMAX = 1605632;

__device__ __align__(16) float g_deg[NMAX];
__device__ __align__(16) float g_dinv[NMAX];
__device__ __align__(16) float g_rcp[NMAX];
__device__ __align__(16) float g_a[NMAX];
__device__ __align__(16) float g_c[NMAX];
__device__ int   g_cnti[NMAX];
__device__ int   g_offs[NMAX];
__device__ int   g_cursor[NMAX];
__device__ int   g_bsums[1024];
__device__ __align__(16) uint2 g_csr[EMAX];   // .x = row idx, .y = norm bits
__device__ __align__(16) int   g_eid[EMAX];
__device__ __align__(16) float g_u[64];
__device__ __align__(16) float g_v[64];
__device__ __align__(16) __half2 g_hh0[(size_t)NMAX * 32];
__device__ __align__(16) __half2 g_hh1[(size_t)NMAX * 32];
__device__ __align__(16) __half2 g_hhT[(size_t)NMAX * 32];  // agg scratch (fp16)
__device__ __align__(16) float g_t1[(size_t)NMAX * L];      // decoder B (fp32)
__device__ int   g_is64;

__device__ __forceinline__ int ld_idx(const void* p, int e, int is64) {
    if (is64) return (int)((const long long*)p)[e];
    return ((const int*)p)[e];
}

// zero deg/cnt + index-dtype detection fused
__global__ void k_zero2(float* pf, int* pi, int n, const unsigned int* er) {
    int i = blockIdx.x * blockDim.x + threadIdx.x;
    if (i < n) { pf[i] = 0.0f; pi[i] = 0; }
    if (blockIdx.x == 0 && threadIdx.x == 0) {
        int ok = 1;
        #pragma unroll
        for (int j = 0; j < 64; j++)
            if (er[2 * j + 1] != 0u) ok = 0;
        g_is64 = ok;
    }
}

__global__ void k_deg_cnt(const float* __restrict__ attr, const void* colp, int E) {
    int is64 = g_is64;
    int e = blockIdx.x * blockDim.x + threadIdx.x;
    if (e < E) {
        int c = ld_idx(colp, e, is64);
        atomicAdd(&g_deg[c], attr[e]);
        atomicAdd(&g_cnti[c], 1);
    }
}

// ---------------- prefix scan over counts -----------------------------------
__global__ void k_scan1(int N) {
    __shared__ int wsum[8];
    int t = threadIdx.x;
    int base = blockIdx.x * 1024 + t * 4;
    int v0 = 0, v1 = 0, v2 = 0, v3 = 0;
    if (base + 0 < N) v0 = g_cnti[base + 0];
    if (base + 1 < N) v1 = g_cnti[base + 1];
    if (base + 2 < N) v2 = g_cnti[base + 2];
    if (base + 3 < N) v3 = g_cnti[base + 3];
    int s = v0 + v1 + v2 + v3;
    int lane = t & 31, warp = t >> 5;
    int x = s;
    #pragma unroll
    for (int o = 1; o < 32; o <<= 1) {
        int y = __shfl_up_sync(0xffffffffu, x, o);
        if (lane >= o) x += y;
    }
    if (lane == 31) wsum[warp] = x;
    __syncthreads();
    if (warp == 0 && lane < 8) {
        int w = wsum[lane];
        #pragma unroll
        for (int o = 1; o < 8; o <<= 1) {
            int y = __shfl_up_sync(0x000000ffu, w, o);
            if (lane >= o) w += y;
        }
        wsum[lane] = w;
    }
    __syncthreads();
    int excl = x - s + (warp > 0 ? wsum[warp - 1] : 0);
    int r = excl;
    r += v0; if (base + 0 < N) g_offs[base + 0] = r;
    r += v1; if (base + 1 < N) g_offs[base + 1] = r;
    r += v2; if (base + 2 < N) g_offs[base + 2] = r;
    r += v3; if (base + 3 < N) g_offs[base + 3] = r;
    if (t == 255) g_bsums[blockIdx.x] = excl + s;
}

__global__ void k_scan2(int nb) {
    if (threadIdx.x == 0 && blockIdx.x == 0) {
        int run = 0;
        for (int i = 0; i < nb; i++) { int t = g_bsums[i]; g_bsums[i] = run; run += t; }
    }
}

__global__ void k_scan3(int N) {
    int i = blockIdx.x * blockDim.x + threadIdx.x;
    if (i < N) {
        int cnt = g_cnti[i];
        int excl = g_offs[i] + g_bsums[i >> 10] - cnt;
        g_offs[i] = excl;
        g_cursor[i] = excl;
        float d = g_deg[i];
        g_dinv[i] = (d > 0.0f) ? rsqrtf(fmaxf(d, 1e-30f)) : 0.0f;
        g_rcp[i]  = 1.0f / fmaxf((float)cnt, 1.0f);
    }
}

__global__ void k_csr_fill(const float* __restrict__ attr, const void* rowp,
                           const void* colp, int E) {
    int is64 = g_is64;
    int e = blockIdx.x * blockDim.x + threadIdx.x;
    if (e < E) {
        int r = ld_idx(rowp, e, is64);
        int c = ld_idx(colp, e, is64);
        int p = atomicAdd(&g_cursor[c], 1);
        uint2 rec;
        rec.x = (unsigned int)r;
        rec.y = __float_as_uint(g_dinv[r] * attr[e] * g_dinv[c]);
        g_csr[p] = rec;
        g_eid[p] = e;
    }
}

__global__ void k_uv(const float* __restrict__ w_enc, const float* __restrict__ b_enc,
                     const float* __restrict__ W) {
    int g = threadIdx.x;
    float u = 0.f, v = 0.f;
    #pragma unroll
    for (int f = 0; f < 64; f++) {
        float wf = W[f * 64 + g];
        u += w_enc[f] * wf;
        v += b_enc[f] * wf;
    }
    g_u[g] = u;
    g_v[g] = v;
}

__global__ void __launch_bounds__(256)
k_l1sums(const float* __restrict__ x, int N) {
    int warp = threadIdx.x >> 5, lane = threadIdx.x & 31;
    int n = blockIdx.x * 8 + warp;
    if (n >= N) return;
    int st = g_offs[n];
    int en = st + g_cnti[n];
    float s1 = 0.f, s0 = 0.f;
    for (int k = st + lane; k < en; k += 32) {
        uint2 rec = g_csr[k];
        float nm = __uint_as_float(rec.y);
        s1 += nm * x[rec.x];
        s0 += nm;
    }
    #pragma unroll
    for (int off = 16; off; off >>= 1) {
        s1 += __shfl_down_sync(0xffffffffu, s1, off);
        s0 += __shfl_down_sync(0xffffffffu, s0, off);
    }
    if (lane == 0) {
        float rcp = g_rcp[n];
        g_a[n] = s1 * rcp;
        g_c[n] = s0 * rcp;
    }
}

__global__ void k_l1out(const float* __restrict__ b1, __half2* __restrict__ hout, int N) {
    int i = blockIdx.x * blockDim.x + threadIdx.x;   // over N*32 half2
    if (i < N * 32) {
        int n = i >> 5, f2 = (i & 31) * 2;
        float an = g_a[n], cn = g_c[n];
        float v0 = fmaxf(an * g_u[f2]     + cn * g_v[f2]     + b1[f2],     0.f);
        float v1 = fmaxf(an * g_u[f2 + 1] + cn * g_v[f2 + 1] + b1[f2 + 1], 0.f);
        hout[i] = __floats2half2_rn(v0, v1);
    }
}

// ---- aggregation over fp16 h -> fp16 out ------------------------------------
__global__ void __launch_bounds__(256)
k_agg(const __half2* __restrict__ hin, __half2* __restrict__ aggo, int N) {
    int warp = threadIdx.x >> 5, lane = threadIdx.x & 31;
    int n = blockIdx.x * 8 + warp;
    if (n >= N) return;
    int g  = lane >> 3;
    int sl = lane & 7;
    int st = g_offs[n];
    int en = st + g_cnti[n];
    float2 a0 = make_float2(0.f, 0.f), a1 = a0, a2 = a0, a3 = a0;
    #pragma unroll 1
    for (int k = st; k < en; k += 4) {
        int e = k + g;
        int ec = e < en - 1 ? e : en - 1;
        uint2 rec = g_csr[ec];
        float nm = (e < en) ? __uint_as_float(rec.y) : 0.f;
        const uint4 v = ((const uint4*)(hin + ((size_t)rec.x << 5)))[sl];
        float2 f0 = __half22float2(*(const __half2*)&v.x);
        float2 f1 = __half22float2(*(const __half2*)&v.y);
        float2 f2 = __half22float2(*(const __half2*)&v.z);
        float2 f3 = __half22float2(*(const __half2*)&v.w);
        a0.x += f0.x * nm; a0.y += f0.y * nm;
        a1.x += f1.x * nm; a1.y += f1.y * nm;
        a2.x += f2.x * nm; a2.y += f2.y * nm;
        a3.x += f3.x * nm; a3.y += f3.y * nm;
    }
    #pragma unroll
    for (int off = 8; off <= 16; off <<= 1) {
        a0.x += __shfl_xor_sync(0xffffffffu, a0.x, off);
        a0.y += __shfl_xor_sync(0xffffffffu, a0.y, off);
        a1.x += __shfl_xor_sync(0xffffffffu, a1.x, off);
        a1.y += __shfl_xor_sync(0xffffffffu, a1.y, off);
        a2.x += __shfl_xor_sync(0xffffffffu, a2.x, off);
        a2.y += __shfl_xor_sync(0xffffffffu, a2.y, off);
        a3.x += __shfl_xor_sync(0xffffffffu, a3.x, off);
        a3.y += __shfl_xor_sync(0xffffffffu, a3.y, off);
    }
    if (lane < 8) {
        float rcp = g_rcp[n];
        __half2 h0 = __floats2half2_rn(a0.x * rcp, a0.y * rcp);
        __half2 h1 = __floats2half2_rn(a1.x * rcp, a1.y * rcp);
        __half2 h2 = __floats2half2_rn(a2.x * rcp, a2.y * rcp);
        __half2 h3 = __floats2half2_rn(a3.x * rcp, a3.y * rcp);
        uint4 o = make_uint4(*(unsigned*)&h0, *(unsigned*)&h1,
                             *(unsigned*)&h2, *(unsigned*)&h3);
        *(uint4*)(aggo + ((size_t)n << 5) + sl * 4) = o;
    }
}

// ---- tensor-core GEMM helpers -----------------------------------------------
__device__ __forceinline__ void mma16816(float* c, unsigned a0, unsigned a1,
                                         unsigned a2, unsigned a3,
                                         unsigned b0, unsigned b1) {
    asm volatile(
        "mma.sync.aligned.m16n8k16.row.col.f32.f16.f16.f32 "
        "{%0,%1,%2,%3}, {%4,%5,%6,%7}, {%8,%9}, {%0,%1,%2,%3};"
        : "+f"(c[0]), "+f"(c[1]), "+f"(c[2]), "+f"(c[3])
        : "r"(a0), "r"(a1), "r"(a2), "r"(a3), "r"(b0), "r"(b1));
}

// ---- MMA GEMM: fp16 X -> fp16 out (+bias, relu), layer GEMM -----------------
__global__ void __launch_bounds__(256)
k_gemm_mma_h2h(const __half2* __restrict__ X, const float* __restrict__ W,
               const float* __restrict__ bias, __half2* __restrict__ Y, int ntiles) {
    __shared__ __half Xs[64][72];
    __shared__ __half Wt[64][72];   // transposed W: Wt[n][k]
    int tid = threadIdx.x;
    int warp = tid >> 5, lane = tid & 31;
    int g = lane >> 2, t = lane & 3;
    int wm = (warp >> 1) * 16;
    int wn = (warp & 1) * 32;
    for (int idx = tid; idx < 4096; idx += 256) {
        int k = idx >> 6, n = idx & 63;
        Wt[n][k] = __float2half(W[idx]);
    }
    float2 bb[4];
    #pragma unroll
    for (int nt = 0; nt < 4; nt++)
        bb[nt] = *(const float2*)(bias + wn + nt * 8 + 2 * t);

    for (int tt = blockIdx.x; tt < ntiles; tt += gridDim.x) {
        __syncthreads();
        size_t hbase = (size_t)tt * 2048;
        const uint4* X4 = (const uint4*)(X + hbase);
        #pragma unroll
        for (int i = 0; i < 2; i++) {
            int idx = tid + i * 256;
            uint4 v = X4[idx];
            int row = idx >> 3;
            int c0  = (idx & 7) * 8;
            *(uint4*)&Xs[row][c0] = v;
        }
        __syncthreads();
        float c[4][4];
        #pragma unroll
        for (int nt = 0; nt < 4; nt++)
            c[nt][0] = c[nt][1] = c[nt][2] = c[nt][3] = 0.f;
        #pragma unroll
        for (int kk = 0; kk < 64; kk += 16) {
            unsigned a0 = *(const unsigned*)&Xs[wm + g][kk + 2 * t];
            unsigned a1 = *(const unsigned*)&Xs[wm + g + 8][kk + 2 * t];
            unsigned a2 = *(const unsigned*)&Xs[wm + g][kk + 2 * t + 8];
            unsigned a3 = *(const unsigned*)&Xs[wm + g + 8][kk + 2 * t + 8];
            #pragma unroll
            for (int nt = 0; nt < 4; nt++) {
                int n = wn + nt * 8 + g;
                unsigned b0 = *(const unsigned*)&Wt[n][kk + 2 * t];
                unsigned b1 = *(const unsigned*)&Wt[n][kk + 2 * t + 8];
                mma16816(c[nt], a0, a1, a2, a3, b0, b1);
            }
        }
        size_t ybase = (size_t)tt * 2048;
        int colh = (wn >> 1) + t;
        #pragma unroll
        for (int nt = 0; nt < 4; nt++) {
            float o0 = fmaxf(c[nt][0] + bb[nt].x, 0.f);
            float o1 = fmaxf(c[nt][1] + bb[nt].y, 0.f);
            float o2 = fmaxf(c[nt][2] + bb[nt].x, 0.f);
            float o3 = fmaxf(c[nt][3] + bb[nt].y, 0.f);
            Y[ybase + (size_t)(wm + g) * 32 + colh + nt * 4]     = __floats2half2_rn(o0, o1);
            Y[ybase + (size_t)(wm + g + 8) * 32 + colh + nt * 4] = __floats2half2_rn(o2, o3);
        }
    }
}

// ---- fused decoder GEMM: fp16 X -> A (fp16, W rows 0..63), B (fp32, 64..127) -
__global__ void __launch_bounds__(256)
k_gemm_mma_dec(const __half2* __restrict__ X, const float* __restrict__ W,
               __half2* __restrict__ YA, float* __restrict__ YB, int ntiles) {
    __shared__ __half Xs[64][72];
    __shared__ __half WtA[64][72];
    __shared__ __half WtB[64][72];
    int tid = threadIdx.x;
    int warp = tid >> 5, lane = tid & 31;
    int g = lane >> 2, t = lane & 3;
    int wm = (warp >> 1) * 16;
    int wn = (warp & 1) * 32;
    for (int idx = tid; idx < 4096; idx += 256) {
        int k = idx >> 6, n = idx & 63;
        WtA[n][k] = __float2half(W[idx]);
        WtB[n][k] = __float2half(W[idx + 4096]);
    }

    for (int tt = blockIdx.x; tt < ntiles; tt += gridDim.x) {
        __syncthreads();
        size_t hbase = (size_t)tt * 2048;
        const uint4* X4 = (const uint4*)(X + hbase);
        #pragma unroll
        for (int i = 0; i < 2; i++) {
            int idx = tid + i * 256;
            uint4 v = X4[idx];
            int row = idx >> 3;
            int c0  = (idx & 7) * 8;
            *(uint4*)&Xs[row][c0] = v;
        }
        __syncthreads();
        float cA[4][4], cB[4][4];
        #pragma unroll
        for (int nt = 0; nt < 4; nt++) {
            cA[nt][0] = cA[nt][1] = cA[nt][2] = cA[nt][3] = 0.f;
            cB[nt][0] = cB[nt][1] = cB[nt][2] = cB[nt][3] = 0.f;
        }
        #pragma unroll
        for (int kk = 0; kk < 64; kk += 16) {
            unsigned a0 = *(const unsigned*)&Xs[wm + g][kk + 2 * t];
            unsigned a1 = *(const unsigned*)&Xs[wm + g + 8][kk + 2 * t];
            unsigned a2 = *(const unsigned*)&Xs[wm + g][kk + 2 * t + 8];
            unsigned a3 = *(const unsigned*)&Xs[wm + g + 8][kk + 2 * t + 8];
            #pragma unroll
            for (int nt = 0; nt < 4; nt++) {
                int n = wn + nt * 8 + g;
                unsigned b0 = *(const unsigned*)&WtA[n][kk + 2 * t];
                unsigned b1 = *(const unsigned*)&WtA[n][kk + 2 * t + 8];
                mma16816(cA[nt], a0, a1, a2, a3, b0, b1);
                unsigned d0 = *(const unsigned*)&WtB[n][kk + 2 * t];
                unsigned d1 = *(const unsigned*)&WtB[n][kk + 2 * t + 8];
                mma16816(cB[nt], a0, a1, a2, a3, d0, d1);
            }
        }
        size_t yab = (size_t)tt * 2048;
        int colh = (wn >> 1) + t;
        #pragma unroll
        for (int nt = 0; nt < 4; nt++) {
            YA[yab + (size_t)(wm + g) * 32 + colh + nt * 4]     = __floats2half2_rn(cA[nt][0], cA[nt][1]);
            YA[yab + (size_t)(wm + g + 8) * 32 + colh + nt * 4] = __floats2half2_rn(cA[nt][2], cA[nt][3]);
        }
        size_t base = (size_t)tt * 4096;
        #pragma unroll
        for (int nt = 0; nt < 4; nt++) {
            int col = wn + nt * 8 + 2 * t;
            *(float2*)(YB + base + (size_t)(wm + g) * 64 + col)     = make_float2(cB[nt][0], cB[nt][1]);
            *(float2*)(YB + base + (size_t)(wm + g + 8) * 64 + col) = make_float2(cB[nt][2], cB[nt][3]);
        }
    }
}

// ---- decoder, CSR order, fp16 A gather --------------------------------------
__global__ void __launch_bounds__(256)
k_dec_csr(const __half2* __restrict__ A, const float* __restrict__ B,
          const float* __restrict__ b1, const float* __restrict__ w2,
          const float* __restrict__ b2, float* __restrict__ out, int N) {
    int warp = threadIdx.x >> 5, lane = threadIdx.x & 31;
    int n = blockIdx.x * 8 + warp;
    if (n >= N) return;
    int lane2 = lane * 2;
    float2 bias = *(const float2*)(b1 + lane2);
    float2 w    = *(const float2*)(w2 + lane2);
    float  bout = b2[0];
    float2 bc   = *(const float2*)(B + ((size_t)n << 6) + lane2);
    bc.x += bias.x; bc.y += bias.y;
    int st = g_offs[n];
    int en = st + g_cnti[n];
    int k = st;
    #pragma unroll 1
    for (; k + 2 <= en; k += 2) {
        uint2 rec0 = g_csr[k];
        uint2 rec1 = g_csr[k + 1];
        int r0 = (int)rec0.x, r1 = (int)rec1.x;
        float2 a0 = __half22float2(A[((size_t)r0 << 5) + lane]);
        float2 a1 = __half22float2(A[((size_t)r1 << 5) + lane]);
        float s0 = fmaxf(a0.x + bc.x, 0.f) * w.x + fmaxf(a0.y + bc.y, 0.f) * w.y;
        float s1 = fmaxf(a1.x + bc.x, 0.f) * w.x + fmaxf(a1.y + bc.y, 0.f) * w.y;
        #pragma unroll
        for (int off = 16; off; off >>= 1) {
            s0 += __shfl_down_sync(0xffffffffu, s0, off);
            s1 += __shfl_down_sync(0xffffffffu, s1, off);
        }
        if (lane == 0) {
            float v0 = s0 + bout;
            float v1 = s1 + bout;
            if (r0 == n) v0 = fmaxf(v0, 0.f) + log1pf(expf(-fabsf(v0)));
            if (r1 == n) v1 = fmaxf(v1, 0.f) + log1pf(expf(-fabsf(v1)));
            out[g_eid[k]]     = v0;
            out[g_eid[k + 1]] = v1;
        }
    }
    if (k < en) {
        uint2 rec = g_csr[k];
        int r = (int)rec.x;
        float2 a = __half22float2(A[((size_t)r << 5) + lane]);
        float s = fmaxf(a.x + bc.x, 0.f) * w.x + fmaxf(a.y + bc.y, 0.f) * w.y;
        #pragma unroll
        for (int off = 16; off; off >>= 1)
            s += __shfl_down_sync(0xffffffffu, s, off);
        if (lane == 0) {
            float val = s + bout;
            if (r == n) val = fmaxf(val, 0.f) + log1pf(expf(-fabsf(val)));
            out[g_eid[k]] = val;
        }
    }
}

extern "C" void kernel_launch(void* const* d_in, const int* in_sizes, int n_in,
                              void* d_out, int out_size) {
    const float* x        = (const float*)d_in[0];
    const float* eattr    = (const float*)d_in[1];
    const float* w_enc    = (const float*)d_in[2];
    const float* b_enc    = (const float*)d_in[3];
    const float* conv1_w  = (const float*)d_in[4];
    const float* conv1_b  = (const float*)d_in[5];
    const float* conv2_w  = (const float*)d_in[6];
    const float* conv2_b  = (const float*)d_in[7];
    const float* dec_w1   = (const float*)d_in[8];
    const float* dec_b1   = (const float*)d_in[9];
    const float* dec_w2   = (const float*)d_in[10];
    const float* dec_b2   = (const float*)d_in[11];
    const void*  rowp     = d_in[12];
    const void*  colp     = d_in[13];
    float* out = (float*)d_out;

    const int N = in_sizes[0];
    const int E = in_sizes[1];

    float *p_deg, *p_t1;
    int *p_cnti;
    __half2 *p_hh0, *p_hh1, *p_hhT;
    cudaGetSymbolAddress((void**)&p_deg, g_deg);
    cudaGetSymbolAddress((void**)&p_t1,  g_t1);
    cudaGetSymbolAddress((void**)&p_cnti, g_cnti);
    cudaGetSymbolAddress((void**)&p_hh0, g_hh0);
    cudaGetSymbolAddress((void**)&p_hh1, g_hh1);
    cudaGetSymbolAddress((void**)&p_hhT, g_hhT);

    const int TB = 256;
    int eb  = (E + TB - 1) / TB;
    int nb  = (N + TB - 1) / TB;
    int nhb = (N * 32 + TB - 1) / TB;
    int ntiles = (N + 63) / 64;
    int gg  = (ntiles + 1) / 2;
    int ab  = (N + 7) / 8;
    int nsb = (N + 1023) / 1024;

    k_zero2<<<nb, TB>>>(p_deg, p_cnti, N, (const unsigned int*)rowp);
    k_deg_cnt<<<eb, TB>>>(eattr, colp, E);

    k_scan1<<<nsb, 256>>>(N);
    k_scan2<<<1, 32>>>(nsb);
    k_scan3<<<nb, TB>>>(N);
    k_csr_fill<<<eb, TB>>>(eattr, rowp, colp, E);

    // layer 1 (collapsed rank-2 form) -> hh0 (fp16)
    k_uv<<<1, 64>>>(w_enc, b_enc, conv1_w);
    k_l1sums<<<ab, TB>>>(x, N);
    k_l1out<<<nhb, TB>>>(conv1_b, p_hh0, N);

    // layers 2..6: agg(fp16 -> fp16 hhT), MMA gemm h2h (hhT -> nxt)
    const float* Ws[5] = { conv2_w,            conv1_w + 4096, conv2_w + 4096,
                           conv1_w + 2*4096,   conv2_w + 2*4096 };
    const float* Bs[5] = { conv2_b,            conv1_b + 64,   conv2_b + 64,
                           conv1_b + 2*64,     conv2_b + 2*64 };
    __half2* cur = p_hh0;
    __half2* nxt = p_hh1;
    for (int i = 0; i < 5; i++) {
        k_agg<<<ab, TB>>>(cur, p_hhT, N);
        k_gemm_mma_h2h<<<gg, TB>>>(p_hhT, Ws[i], Bs[i], nxt, ntiles);
        { __half2* t = cur; cur = nxt; nxt = t; }
    }
    // after 5 layers: cur = hh1, nxt = hh0 (free)

    // fused decoder GEMM: A (fp16) -> nxt, B (fp32) -> t1
    k_gemm_mma_dec<<<gg, TB>>>(cur, dec_w1, nxt, p_t1, ntiles);
    k_dec_csr<<<ab, TB>>>(nxt, p_t1, dec_b1, dec_w2, dec_b2, out, N);
}